// round 1
// baseline (speedup 1.0000x reference)
#include <cuda_runtime.h>
#include <cstdint>

#define DI __device__ __forceinline__

DI unsigned f2t(float x) { unsigned u; asm("cvt.rna.tf32.f32 %0, %1;" : "=r"(u) : "f"(x)); return u; }

DI void mma8(float c[4], const unsigned a[4], const unsigned b[2]) {
    asm("mma.sync.aligned.m16n8k8.row.col.f32.tf32.tf32.f32 "
        "{%0,%1,%2,%3}, {%4,%5,%6,%7}, {%8,%9}, {%0,%1,%2,%3};"
        : "+f"(c[0]), "+f"(c[1]), "+f"(c[2]), "+f"(c[3])
        : "r"(a[0]), "r"(a[1]), "r"(a[2]), "r"(a[3]), "r"(b[0]), "r"(b[1]));
}

// ---- scratch (device globals; no allocations allowed) ----
__device__ float g_fc1[2][4096 * 256];
__device__ float g_fc2[2][4096 * 128];
__device__ float g_h  [2][4096 * 64];
__device__ float g_ht [2][64 * 4096];
__device__ float g_new[2][4096 * 64];
__device__ float g_part[512];

// ============================================================================
// GEMM  C[m,n] = sum_k A[m,k] * B[n,k] + bias[n]   (A: MxK row-major,
// B: NxK row-major == "row.col" for mma). NS=1: plain tf32; NS=2: split-tf32
// (hi/lo) -> ~fp32 accuracy with 3 mmas per tile.
// Warp tile = 32x32 (2 x m16 tiles, 4 x n8 tiles). gridDim.z selects graph.
// ============================================================================
template<int BM, int BN, int BK, int NS, bool RELU, bool WT>
__global__ void __launch_bounds__((BM / 32) * (BN / 32) * 32)
gemm_tn(const float* __restrict__ A0, const float* __restrict__ A1,
        const float* __restrict__ B0, const float* __restrict__ B1,
        const float* __restrict__ bias0, const float* __restrict__ bias1,
        float* __restrict__ C0, float* __restrict__ C1,
        float* __restrict__ T0, float* __restrict__ T1,
        int M, int N, int K)
{
    constexpr int WM = BM / 32, WN = BN / 32, NW = WM * WN, NT = NW * 32;
    constexpr int LD = BK + 4;
    constexpr int F4 = BK / 4, RA = NT / F4, PA = BM / RA, PB = BN / RA;
    static_assert(BM % RA == 0 && BN % RA == 0, "tile div");

    const int z = blockIdx.z;
    const float* A = z ? A1 : A0;
    const float* B = z ? B1 : B0;
    const float* bias = z ? bias1 : bias0;
    float* C = z ? C1 : C0;
    float* T = z ? T1 : T0;

    __shared__ unsigned As[NS][BM][LD];
    __shared__ unsigned Bs[NS][BN][LD];

    const int tid = threadIdx.x, warp = tid >> 5, lane = tid & 31;
    const int wm = warp % WM, wn = warp / WM;
    const int gid = lane >> 2, tig = lane & 3;
    const size_t m0 = (size_t)blockIdx.x * BM;
    const size_t n0 = (size_t)blockIdx.y * BN;
    const int ax = tid % F4, ay = tid / F4;

    float acc[2][4][4];
#pragma unroll
    for (int i = 0; i < 2; i++)
#pragma unroll
        for (int j = 0; j < 4; j++)
#pragma unroll
            for (int e = 0; e < 4; e++) acc[i][j][e] = 0.f;

    // prologue: prefetch first tile into registers
    float4 ra[PA], rb[PB];
#pragma unroll
    for (int p = 0; p < PA; p++)
        ra[p] = *(const float4*)(A + (m0 + p * RA + ay) * K + ax * 4);
#pragma unroll
    for (int p = 0; p < PB; p++)
        rb[p] = *(const float4*)(B + (n0 + p * RA + ay) * K + ax * 4);

    for (int k0 = 0; k0 < K; k0 += BK) {
        // store current registers -> smem (with tf32 conversion, + lo part if split)
#pragma unroll
        for (int p = 0; p < PA; p++) {
            int row = p * RA + ay;
            unsigned h0 = f2t(ra[p].x), h1 = f2t(ra[p].y), h2 = f2t(ra[p].z), h3 = f2t(ra[p].w);
            As[0][row][ax * 4 + 0] = h0; As[0][row][ax * 4 + 1] = h1;
            As[0][row][ax * 4 + 2] = h2; As[0][row][ax * 4 + 3] = h3;
            if (NS == 2) {
                As[NS - 1][row][ax * 4 + 0] = f2t(ra[p].x - __uint_as_float(h0));
                As[NS - 1][row][ax * 4 + 1] = f2t(ra[p].y - __uint_as_float(h1));
                As[NS - 1][row][ax * 4 + 2] = f2t(ra[p].z - __uint_as_float(h2));
                As[NS - 1][row][ax * 4 + 3] = f2t(ra[p].w - __uint_as_float(h3));
            }
        }
#pragma unroll
        for (int p = 0; p < PB; p++) {
            int row = p * RA + ay;
            unsigned h0 = f2t(rb[p].x), h1 = f2t(rb[p].y), h2 = f2t(rb[p].z), h3 = f2t(rb[p].w);
            Bs[0][row][ax * 4 + 0] = h0; Bs[0][row][ax * 4 + 1] = h1;
            Bs[0][row][ax * 4 + 2] = h2; Bs[0][row][ax * 4 + 3] = h3;
            if (NS == 2) {
                Bs[NS - 1][row][ax * 4 + 0] = f2t(rb[p].x - __uint_as_float(h0));
                Bs[NS - 1][row][ax * 4 + 1] = f2t(rb[p].y - __uint_as_float(h1));
                Bs[NS - 1][row][ax * 4 + 2] = f2t(rb[p].z - __uint_as_float(h2));
                Bs[NS - 1][row][ax * 4 + 3] = f2t(rb[p].w - __uint_as_float(h3));
            }
        }
        __syncthreads();

        // prefetch next tile (LDG in flight during the mma work below)
        if (k0 + BK < K) {
#pragma unroll
            for (int p = 0; p < PA; p++)
                ra[p] = *(const float4*)(A + (m0 + p * RA + ay) * K + (k0 + BK) + ax * 4);
#pragma unroll
            for (int p = 0; p < PB; p++)
                rb[p] = *(const float4*)(B + (n0 + p * RA + ay) * K + (k0 + BK) + ax * 4);
        }

#pragma unroll
        for (int ks = 0; ks < BK / 8; ks++) {
            unsigned af[NS][2][4], bf[NS][4][2];
#pragma unroll
            for (int s = 0; s < NS; s++) {
#pragma unroll
                for (int mt = 0; mt < 2; mt++) {
                    int rr = wm * 32 + mt * 16 + gid;
                    af[s][mt][0] = As[s][rr    ][ks * 8 + tig];
                    af[s][mt][1] = As[s][rr + 8][ks * 8 + tig];
                    af[s][mt][2] = As[s][rr    ][ks * 8 + tig + 4];
                    af[s][mt][3] = As[s][rr + 8][ks * 8 + tig + 4];
                }
#pragma unroll
                for (int nt = 0; nt < 4; nt++) {
                    int cc = wn * 32 + nt * 8 + gid;
                    bf[s][nt][0] = Bs[s][cc][ks * 8 + tig];
                    bf[s][nt][1] = Bs[s][cc][ks * 8 + tig + 4];
                }
            }
#pragma unroll
            for (int mt = 0; mt < 2; mt++)
#pragma unroll
                for (int nt = 0; nt < 4; nt++) {
                    mma8(acc[mt][nt], af[0][mt], bf[0][nt]);
                    if (NS == 2) {
                        mma8(acc[mt][nt], af[0][mt], bf[NS - 1][nt]);
                        mma8(acc[mt][nt], af[NS - 1][mt], bf[0][nt]);
                    }
                }
        }
        __syncthreads();
    }

    // epilogue
#pragma unroll
    for (int mt = 0; mt < 2; mt++) {
#pragma unroll
        for (int nt = 0; nt < 4; nt++) {
            size_t row = m0 + wm * 32 + mt * 16 + gid;
            size_t col = n0 + wn * 32 + nt * 8 + tig * 2;
#pragma unroll
            for (int e = 0; e < 4; e++) {
                size_t r = row + (size_t)(e >> 1) * 8;
                size_t c = col + (size_t)(e & 1);
                float v = acc[mt][nt][e] + bias[c];
                if (RELU) v = fmaxf(v, 0.f);
                C[r * N + c] = v;
                if (WT) T[c * (size_t)M + r] = v;
            }
        }
    }
}

// ============================================================================
// Masked-weighted aggregation:
//   agg[i,c] = sum_j (adj[i,j]==1 ? alpha[i,j] : 0) * h[j,c]     (B = h^T)
//   out[i,c] = deg_i==0 ? 0 : agg*W00/deg_i + h[i,c]
// Each block owns full K for its BM rows -> deg computed in-block.
// ============================================================================
template<int BM, int BN, int BK>
__global__ void __launch_bounds__((BM / 32) * (BN / 32) * 32)
agg_tn(const int* __restrict__ adjA, const int* __restrict__ adjB,
       const float* __restrict__ alpha,
       const float* __restrict__ HtA, const float* __restrict__ HtB,
       const float* __restrict__ HA, const float* __restrict__ HB,
       const float* __restrict__ Wp,
       float* __restrict__ OA, float* __restrict__ OB, int K)
{
    constexpr int WM = BM / 32, WN = BN / 32, NW = WM * WN, NT = NW * 32;
    constexpr int LD = BK + 4;
    constexpr int F4 = BK / 4, RA = NT / F4, PA = BM / RA, PB = BN / RA;

    const int z = blockIdx.z;
    const int* adj = z ? adjB : adjA;
    const float* Ht = z ? HtB : HtA;
    const float* H  = z ? HB  : HA;
    float* O = z ? OB : OA;

    __shared__ unsigned As[BM][LD];
    __shared__ unsigned Bs[BN][LD];
    __shared__ int sdeg[BM];

    const int tid = threadIdx.x, warp = tid >> 5, lane = tid & 31;
    const int wm = warp % WM, wn = warp / WM;
    const int gid = lane >> 2, tig = lane & 3;
    const size_t m0 = (size_t)blockIdx.x * BM;
    const int ax = tid % F4, ay = tid / F4;

    if (tid < BM) sdeg[tid] = 0;

    float acc[2][4][4];
#pragma unroll
    for (int i = 0; i < 2; i++)
#pragma unroll
        for (int j = 0; j < 4; j++)
#pragma unroll
            for (int e = 0; e < 4; e++) acc[i][j][e] = 0.f;

    int cnt[PA];
#pragma unroll
    for (int p = 0; p < PA; p++) cnt[p] = 0;

    int4 rma[PA]; float4 rva[PA]; float4 rb[PB];
#pragma unroll
    for (int p = 0; p < PA; p++) {
        size_t g = (m0 + p * RA + ay) * (size_t)K + ax * 4;
        rma[p] = *(const int4*)(adj + g);
        rva[p] = *(const float4*)(alpha + g);
    }
#pragma unroll
    for (int p = 0; p < PB; p++)
        rb[p] = *(const float4*)(Ht + (size_t)(p * RA + ay) * K + ax * 4);

    for (int k0 = 0; k0 < K; k0 += BK) {
#pragma unroll
        for (int p = 0; p < PA; p++) {
            int row = p * RA + ay;
            int mx = (rma[p].x == 1), my = (rma[p].y == 1);
            int mz = (rma[p].z == 1), mw = (rma[p].w == 1);
            cnt[p] += mx + my + mz + mw;
            As[row][ax * 4 + 0] = f2t(mx ? rva[p].x : 0.f);
            As[row][ax * 4 + 1] = f2t(my ? rva[p].y : 0.f);
            As[row][ax * 4 + 2] = f2t(mz ? rva[p].z : 0.f);
            As[row][ax * 4 + 3] = f2t(mw ? rva[p].w : 0.f);
        }
#pragma unroll
        for (int p = 0; p < PB; p++) {
            int row = p * RA + ay;
            Bs[row][ax * 4 + 0] = f2t(rb[p].x);
            Bs[row][ax * 4 + 1] = f2t(rb[p].y);
            Bs[row][ax * 4 + 2] = f2t(rb[p].z);
            Bs[row][ax * 4 + 3] = f2t(rb[p].w);
        }
        __syncthreads();

        if (k0 + BK < K) {
#pragma unroll
            for (int p = 0; p < PA; p++) {
                size_t g = (m0 + p * RA + ay) * (size_t)K + (k0 + BK) + ax * 4;
                rma[p] = *(const int4*)(adj + g);
                rva[p] = *(const float4*)(alpha + g);
            }
#pragma unroll
            for (int p = 0; p < PB; p++)
                rb[p] = *(const float4*)(Ht + (size_t)(p * RA + ay) * K + (k0 + BK) + ax * 4);
        }

#pragma unroll
        for (int ks = 0; ks < BK / 8; ks++) {
            unsigned af[2][4], bf[4][2];
#pragma unroll
            for (int mt = 0; mt < 2; mt++) {
                int rr = wm * 32 + mt * 16 + gid;
                af[mt][0] = As[rr    ][ks * 8 + tig];
                af[mt][1] = As[rr + 8][ks * 8 + tig];
                af[mt][2] = As[rr    ][ks * 8 + tig + 4];
                af[mt][3] = As[rr + 8][ks * 8 + tig + 4];
            }
#pragma unroll
            for (int nt = 0; nt < 4; nt++) {
                int cc = wn * 32 + nt * 8 + gid;
                bf[nt][0] = Bs[cc][ks * 8 + tig];
                bf[nt][1] = Bs[cc][ks * 8 + tig + 4];
            }
#pragma unroll
            for (int mt = 0; mt < 2; mt++)
#pragma unroll
                for (int nt = 0; nt < 4; nt++)
                    mma8(acc[mt][nt], af[mt], bf[nt]);
        }
        __syncthreads();
    }

#pragma unroll
    for (int p = 0; p < PA; p++) atomicAdd(&sdeg[p * RA + ay], cnt[p]);
    __syncthreads();

    const float W00 = Wp[0];
#pragma unroll
    for (int mt = 0; mt < 2; mt++) {
#pragma unroll
        for (int nt = 0; nt < 4; nt++) {
#pragma unroll
            for (int e = 0; e < 4; e++) {
                int rl = wm * 32 + mt * 16 + gid + (e >> 1) * 8;
                size_t r = m0 + rl;
                size_t c = wn * 32 + nt * 8 + tig * 2 + (e & 1);
                int d = sdeg[rl];
                float hv = H[r * 64 + c];
                float v = d ? acc[mt][nt][e] * W00 / (float)d + hv : 0.f;
                O[r * 64 + c] = v;
            }
        }
    }
}

// ============================================================================
// Classifier: out[c] = clf_b[c] + sum_i feat_i * clf_w[c, i]
// Deterministic two-stage reduction (no float atomics).
// ============================================================================
__global__ void clf_partial(const float* __restrict__ n0f, const float* __restrict__ n1f,
                            const float* __restrict__ w, float* __restrict__ part)
{
    const int L = 4096 * 64;          // per-graph feature length
    const int TOT = 2 * L;            // 524288
    const int chunk = 2048;           // TOT / 256 blocks
    int base = blockIdx.x * chunk;
    float s0 = 0.f, s1 = 0.f;
    for (int i = base + threadIdx.x; i < base + chunk; i += blockDim.x) {
        float f = (i < L) ? n0f[i] : n1f[i - L];
        s0 += f * w[i];
        s1 += f * w[TOT + i];
    }
    __shared__ float sm[8][2];
#pragma unroll
    for (int o = 16; o; o >>= 1) {
        s0 += __shfl_down_sync(0xffffffffu, s0, o);
        s1 += __shfl_down_sync(0xffffffffu, s1, o);
    }
    if ((threadIdx.x & 31) == 0) { sm[threadIdx.x >> 5][0] = s0; sm[threadIdx.x >> 5][1] = s1; }
    __syncthreads();
    if (threadIdx.x == 0) {
        float a = 0.f, b = 0.f;
        for (int i = 0; i < (int)(blockDim.x >> 5); i++) { a += sm[i][0]; b += sm[i][1]; }
        part[blockIdx.x * 2 + 0] = a;
        part[blockIdx.x * 2 + 1] = b;
    }
}

__global__ void clf_final(const float* __restrict__ part, const float* __restrict__ bias,
                          float* __restrict__ out, int nb)
{
    float s0 = 0.f, s1 = 0.f;
    for (int i = threadIdx.x; i < nb; i += blockDim.x) { s0 += part[i * 2]; s1 += part[i * 2 + 1]; }
    __shared__ float sm[8][2];
#pragma unroll
    for (int o = 16; o; o >>= 1) {
        s0 += __shfl_down_sync(0xffffffffu, s0, o);
        s1 += __shfl_down_sync(0xffffffffu, s1, o);
    }
    if ((threadIdx.x & 31) == 0) { sm[threadIdx.x >> 5][0] = s0; sm[threadIdx.x >> 5][1] = s1; }
    __syncthreads();
    if (threadIdx.x == 0) {
        float a = 0.f, b = 0.f;
        for (int i = 0; i < (int)(blockDim.x >> 5); i++) { a += sm[i][0]; b += sm[i][1]; }
        out[0] = a + bias[0];
        out[1] = b + bias[1];
    }
}

// ============================================================================
extern "C" void kernel_launch(void* const* d_in, const int* in_sizes, int n_in,
                              void* d_out, int out_size)
{
    const float* x1    = (const float*)d_in[0];
    const float* x2    = (const float*)d_in[1];
    const int*   adj1  = (const int*)d_in[2];
    const int*   adj2  = (const int*)d_in[3];
    const float* e1_w1 = (const float*)d_in[4];
    const float* e1_b1 = (const float*)d_in[5];
    const float* e1_w2 = (const float*)d_in[6];
    const float* e1_b2 = (const float*)d_in[7];
    const float* e1_w3 = (const float*)d_in[8];
    const float* e1_b3 = (const float*)d_in[9];
    const float* e2_w1 = (const float*)d_in[10];
    const float* e2_b1 = (const float*)d_in[11];
    const float* e2_w2 = (const float*)d_in[12];
    const float* e2_b2 = (const float*)d_in[13];
    const float* e2_w3 = (const float*)d_in[14];
    const float* e2_b3 = (const float*)d_in[15];
    const float* W     = (const float*)d_in[16];
    const float* alpha = (const float*)d_in[17];
    const float* clf_w = (const float*)d_in[18];
    const float* clf_b = (const float*)d_in[19];

    float *fc1p, *fc2p, *hp, *htp, *newp, *partp;
    cudaGetSymbolAddress((void**)&fc1p,  g_fc1);
    cudaGetSymbolAddress((void**)&fc2p,  g_fc2);
    cudaGetSymbolAddress((void**)&hp,    g_h);
    cudaGetSymbolAddress((void**)&htp,   g_ht);
    cudaGetSymbolAddress((void**)&newp,  g_new);
    cudaGetSymbolAddress((void**)&partp, g_part);

    // fc1: [4096,4096] x [256,4096]^T -> [4096,256]   (tf32, NS=1)
    gemm_tn<64, 128, 32, 1, false, false><<<dim3(64, 2, 2), 256>>>(
        x1, x2, e1_w1, e2_w1, e1_b1, e2_b1,
        fc1p, fc1p + 4096 * 256, nullptr, nullptr, 4096, 256, 4096);

    // fc2: [4096,256] x [128,256]^T -> [4096,128]     (split-tf32, NS=2)
    gemm_tn<64, 64, 32, 2, false, false><<<dim3(64, 2, 2), 128>>>(
        fc1p, fc1p + 4096 * 256, e1_w2, e2_w2, e1_b2, e2_b2,
        fc2p, fc2p + 4096 * 128, nullptr, nullptr, 4096, 128, 256);

    // fc3+relu: [4096,128] x [64,128]^T -> [4096,64] (+ transposed copy)
    gemm_tn<64, 64, 32, 2, true, true><<<dim3(64, 1, 2), 128>>>(
        fc2p, fc2p + 4096 * 128, e1_w3, e2_w3, e1_b3, e2_b3,
        hp, hp + 4096 * 64, htp, htp + 64 * 4096, 4096, 64, 128);

    // masked aggregation + residual + deg masking
    agg_tn<64, 64, 32><<<dim3(64, 1, 2), 128>>>(
        adj1, adj2, alpha, htp, htp + 64 * 4096, hp, hp + 4096 * 64, W,
        newp, newp + 4096 * 64, 4096);

    // classifier
    clf_partial<<<256, 256>>>(newp, newp + 4096 * 64, clf_w, partp);
    clf_final<<<1, 256>>>(partp, clf_b, (float*)d_out, 256);

    (void)in_sizes; (void)n_in; (void)out_size;
}

// round 2
// speedup vs baseline: 1.2337x; 1.2337x over previous
#include <cuda_runtime.h>
#include <cstdint>

#define DI __device__ __forceinline__

DI unsigned f2t(float x) { unsigned u; asm("cvt.rna.tf32.f32 %0, %1;" : "=r"(u) : "f"(x)); return u; }

DI void mma8(float c[4], const unsigned a[4], const unsigned b[2]) {
    asm("mma.sync.aligned.m16n8k8.row.col.f32.tf32.tf32.f32 "
        "{%0,%1,%2,%3}, {%4,%5,%6,%7}, {%8,%9}, {%0,%1,%2,%3};"
        : "+f"(c[0]), "+f"(c[1]), "+f"(c[2]), "+f"(c[3])
        : "r"(a[0]), "r"(a[1]), "r"(a[2]), "r"(a[3]), "r"(b[0]), "r"(b[1]));
}

// ---- scratch (device globals; no allocations allowed) ----
#define KC 8                       // split-K factor for aggregation
__device__ float g_fc1[2][4096 * 256];
__device__ float g_fc2[2][4096 * 128];
__device__ float g_h  [2][4096 * 64];
__device__ float g_ht [2][64 * 4096];
__device__ float g_new[2][4096 * 64];
__device__ float g_aggp[2][KC][4096 * 64];
__device__ int   g_degp[2][KC][4096];
__device__ float g_part[512];

// ============================================================================
// Pipelined (double-buffered smem) TF32 GEMM:
//   C[m,n] = sum_k A[m,k]*B[n,k] + bias[n]
// BM=BN=64, BK=32, 128 threads (4 warps, 32x32 warp tiles).
// grid: (x = n-tile [fastest -> A-tile L2 reuse], y = m-tile, z = graph)
// ============================================================================
template<int BM, int BN, int BK>
__global__ void __launch_bounds__(128)
gemm_pipe(const float* __restrict__ A0, const float* __restrict__ A1,
          const float* __restrict__ B0, const float* __restrict__ B1,
          const float* __restrict__ bias0, const float* __restrict__ bias1,
          float* __restrict__ C0, float* __restrict__ C1,
          int M, int N, int K)
{
    constexpr int WM = BM / 32, WN = BN / 32;
    constexpr int NT = WM * WN * 32;
    constexpr int LD = BK + 4;
    constexpr int F4 = BK / 4, RA = NT / F4, PA = BM / RA, PB = BN / RA;

    const int z = blockIdx.z;
    const float* A = z ? A1 : A0;
    const float* B = z ? B1 : B0;
    const float* bias = z ? bias1 : bias0;
    float* C = z ? C1 : C0;

    __shared__ unsigned As[2][BM][LD];
    __shared__ unsigned Bs[2][BN][LD];

    const int tid = threadIdx.x, warp = tid >> 5, lane = tid & 31;
    const int wm = warp % WM, wn = warp / WM;
    const int gid = lane >> 2, tig = lane & 3;
    const size_t m0 = (size_t)blockIdx.y * BM;
    const size_t n0 = (size_t)blockIdx.x * BN;
    const int ax = tid % F4, ay = tid / F4;

    float acc[WM][WN * 2][4];
#pragma unroll
    for (int i = 0; i < WM; i++)
#pragma unroll
        for (int j = 0; j < WN * 2; j++)
#pragma unroll
            for (int e = 0; e < 4; e++) acc[i][j][e] = 0.f;

    float4 ra[PA], rb[PB];
    const int nIter = K / BK;

    // prologue: tile0 -> regs -> buf0 ; tile1 -> regs
#pragma unroll
    for (int p = 0; p < PA; p++)
        ra[p] = *(const float4*)(A + (m0 + p * RA + ay) * K + ax * 4);
#pragma unroll
    for (int p = 0; p < PB; p++)
        rb[p] = *(const float4*)(B + (n0 + p * RA + ay) * K + ax * 4);
#pragma unroll
    for (int p = 0; p < PA; p++) {
        int row = p * RA + ay;
        As[0][row][ax * 4 + 0] = f2t(ra[p].x); As[0][row][ax * 4 + 1] = f2t(ra[p].y);
        As[0][row][ax * 4 + 2] = f2t(ra[p].z); As[0][row][ax * 4 + 3] = f2t(ra[p].w);
    }
#pragma unroll
    for (int p = 0; p < PB; p++) {
        int row = p * RA + ay;
        Bs[0][row][ax * 4 + 0] = f2t(rb[p].x); Bs[0][row][ax * 4 + 1] = f2t(rb[p].y);
        Bs[0][row][ax * 4 + 2] = f2t(rb[p].z); Bs[0][row][ax * 4 + 3] = f2t(rb[p].w);
    }
    if (nIter > 1) {
#pragma unroll
        for (int p = 0; p < PA; p++)
            ra[p] = *(const float4*)(A + (m0 + p * RA + ay) * K + BK + ax * 4);
#pragma unroll
        for (int p = 0; p < PB; p++)
            rb[p] = *(const float4*)(B + (n0 + p * RA + ay) * K + BK + ax * 4);
    }
    __syncthreads();

    for (int it = 0; it < nIter; it++) {
        const int cur = it & 1;
        // stage next tile from regs into the other buffer (overlaps with mma)
        if (it + 1 < nIter) {
#pragma unroll
            for (int p = 0; p < PA; p++) {
                int row = p * RA + ay;
                As[cur ^ 1][row][ax * 4 + 0] = f2t(ra[p].x); As[cur ^ 1][row][ax * 4 + 1] = f2t(ra[p].y);
                As[cur ^ 1][row][ax * 4 + 2] = f2t(ra[p].z); As[cur ^ 1][row][ax * 4 + 3] = f2t(ra[p].w);
            }
#pragma unroll
            for (int p = 0; p < PB; p++) {
                int row = p * RA + ay;
                Bs[cur ^ 1][row][ax * 4 + 0] = f2t(rb[p].x); Bs[cur ^ 1][row][ax * 4 + 1] = f2t(rb[p].y);
                Bs[cur ^ 1][row][ax * 4 + 2] = f2t(rb[p].z); Bs[cur ^ 1][row][ax * 4 + 3] = f2t(rb[p].w);
            }
        }
        // prefetch tile it+2 into regs (LDG latency hidden by mma below)
        if (it + 2 < nIter) {
            const size_t ko = (size_t)(it + 2) * BK;
#pragma unroll
            for (int p = 0; p < PA; p++)
                ra[p] = *(const float4*)(A + (m0 + p * RA + ay) * K + ko + ax * 4);
#pragma unroll
            for (int p = 0; p < PB; p++)
                rb[p] = *(const float4*)(B + (n0 + p * RA + ay) * K + ko + ax * 4);
        }
#pragma unroll
        for (int ks = 0; ks < BK / 8; ks++) {
            unsigned af[WM][4], bf[WN * 2][2];
#pragma unroll
            for (int mt = 0; mt < WM; mt++) {
                int rr = wm * 32 + mt * 16 + gid;
                af[mt][0] = As[cur][rr    ][ks * 8 + tig];
                af[mt][1] = As[cur][rr + 8][ks * 8 + tig];
                af[mt][2] = As[cur][rr    ][ks * 8 + tig + 4];
                af[mt][3] = As[cur][rr + 8][ks * 8 + tig + 4];
            }
#pragma unroll
            for (int nt = 0; nt < WN * 2; nt++) {
                int cc = wn * 32 + nt * 8 + gid;
                bf[nt][0] = Bs[cur][cc][ks * 8 + tig];
                bf[nt][1] = Bs[cur][cc][ks * 8 + tig + 4];
            }
#pragma unroll
            for (int mt = 0; mt < WM; mt++)
#pragma unroll
                for (int nt = 0; nt < WN * 2; nt++)
                    mma8(acc[mt][nt], af[mt], bf[nt]);
        }
        __syncthreads();
    }

#pragma unroll
    for (int mt = 0; mt < WM; mt++)
#pragma unroll
        for (int nt = 0; nt < WN * 2; nt++) {
            size_t row = m0 + wm * 32 + mt * 16 + gid;
            size_t col = n0 + wn * 32 + nt * 8 + tig * 2;
#pragma unroll
            for (int e = 0; e < 4; e++) {
                size_t r = row + (size_t)(e >> 1) * 8;
                size_t c = col + (size_t)(e & 1);
                C[r * N + c] = acc[mt][nt][e] + bias[c];
            }
        }
}

// ============================================================================
// Original single-buffered GEMM, kept for fc2/fc3 (split-tf32, cheap layers)
// ============================================================================
template<int BM, int BN, int BK, int NS, bool RELU, bool WT>
__global__ void __launch_bounds__((BM / 32) * (BN / 32) * 32)
gemm_tn(const float* __restrict__ A0, const float* __restrict__ A1,
        const float* __restrict__ B0, const float* __restrict__ B1,
        const float* __restrict__ bias0, const float* __restrict__ bias1,
        float* __restrict__ C0, float* __restrict__ C1,
        float* __restrict__ T0, float* __restrict__ T1,
        int M, int N, int K)
{
    constexpr int WM = BM / 32, WN = BN / 32, NW = WM * WN, NT = NW * 32;
    constexpr int LD = BK + 4;
    constexpr int F4 = BK / 4, RA = NT / F4, PA = BM / RA, PB = BN / RA;

    const int z = blockIdx.z;
    const float* A = z ? A1 : A0;
    const float* B = z ? B1 : B0;
    const float* bias = z ? bias1 : bias0;
    float* C = z ? C1 : C0;
    float* T = z ? T1 : T0;

    __shared__ unsigned As[NS][BM][LD];
    __shared__ unsigned Bs[NS][BN][LD];

    const int tid = threadIdx.x, warp = tid >> 5, lane = tid & 31;
    const int wm = warp % WM, wn = warp / WM;
    const int gid = lane >> 2, tig = lane & 3;
    const size_t m0 = (size_t)blockIdx.x * BM;
    const size_t n0 = (size_t)blockIdx.y * BN;
    const int ax = tid % F4, ay = tid / F4;

    float acc[2][4][4];
#pragma unroll
    for (int i = 0; i < 2; i++)
#pragma unroll
        for (int j = 0; j < 4; j++)
#pragma unroll
            for (int e = 0; e < 4; e++) acc[i][j][e] = 0.f;

    float4 ra[PA], rb[PB];
#pragma unroll
    for (int p = 0; p < PA; p++)
        ra[p] = *(const float4*)(A + (m0 + p * RA + ay) * K + ax * 4);
#pragma unroll
    for (int p = 0; p < PB; p++)
        rb[p] = *(const float4*)(B + (n0 + p * RA + ay) * K + ax * 4);

    for (int k0 = 0; k0 < K; k0 += BK) {
#pragma unroll
        for (int p = 0; p < PA; p++) {
            int row = p * RA + ay;
            unsigned h0 = f2t(ra[p].x), h1 = f2t(ra[p].y), h2 = f2t(ra[p].z), h3 = f2t(ra[p].w);
            As[0][row][ax * 4 + 0] = h0; As[0][row][ax * 4 + 1] = h1;
            As[0][row][ax * 4 + 2] = h2; As[0][row][ax * 4 + 3] = h3;
            if (NS == 2) {
                As[NS - 1][row][ax * 4 + 0] = f2t(ra[p].x - __uint_as_float(h0));
                As[NS - 1][row][ax * 4 + 1] = f2t(ra[p].y - __uint_as_float(h1));
                As[NS - 1][row][ax * 4 + 2] = f2t(ra[p].z - __uint_as_float(h2));
                As[NS - 1][row][ax * 4 + 3] = f2t(ra[p].w - __uint_as_float(h3));
            }
        }
#pragma unroll
        for (int p = 0; p < PB; p++) {
            int row = p * RA + ay;
            unsigned h0 = f2t(rb[p].x), h1 = f2t(rb[p].y), h2 = f2t(rb[p].z), h3 = f2t(rb[p].w);
            Bs[0][row][ax * 4 + 0] = h0; Bs[0][row][ax * 4 + 1] = h1;
            Bs[0][row][ax * 4 + 2] = h2; Bs[0][row][ax * 4 + 3] = h3;
            if (NS == 2) {
                Bs[NS - 1][row][ax * 4 + 0] = f2t(rb[p].x - __uint_as_float(h0));
                Bs[NS - 1][row][ax * 4 + 1] = f2t(rb[p].y - __uint_as_float(h1));
                Bs[NS - 1][row][ax * 4 + 2] = f2t(rb[p].z - __uint_as_float(h2));
                Bs[NS - 1][row][ax * 4 + 3] = f2t(rb[p].w - __uint_as_float(h3));
            }
        }
        __syncthreads();

        if (k0 + BK < K) {
#pragma unroll
            for (int p = 0; p < PA; p++)
                ra[p] = *(const float4*)(A + (m0 + p * RA + ay) * K + (k0 + BK) + ax * 4);
#pragma unroll
            for (int p = 0; p < PB; p++)
                rb[p] = *(const float4*)(B + (n0 + p * RA + ay) * K + (k0 + BK) + ax * 4);
        }

#pragma unroll
        for (int ks = 0; ks < BK / 8; ks++) {
            unsigned af[NS][2][4], bf[NS][4][2];
#pragma unroll
            for (int s = 0; s < NS; s++) {
#pragma unroll
                for (int mt = 0; mt < 2; mt++) {
                    int rr = wm * 32 + mt * 16 + gid;
                    af[s][mt][0] = As[s][rr    ][ks * 8 + tig];
                    af[s][mt][1] = As[s][rr + 8][ks * 8 + tig];
                    af[s][mt][2] = As[s][rr    ][ks * 8 + tig + 4];
                    af[s][mt][3] = As[s][rr + 8][ks * 8 + tig + 4];
                }
#pragma unroll
                for (int nt = 0; nt < 4; nt++) {
                    int cc = wn * 32 + nt * 8 + gid;
                    bf[s][nt][0] = Bs[s][cc][ks * 8 + tig];
                    bf[s][nt][1] = Bs[s][cc][ks * 8 + tig + 4];
                }
            }
#pragma unroll
            for (int mt = 0; mt < 2; mt++)
#pragma unroll
                for (int nt = 0; nt < 4; nt++) {
                    mma8(acc[mt][nt], af[0][mt], bf[0][nt]);
                    if (NS == 2) {
                        mma8(acc[mt][nt], af[0][mt], bf[NS - 1][nt]);
                        mma8(acc[mt][nt], af[NS - 1][mt], bf[0][nt]);
                    }
                }
        }
        __syncthreads();
    }

#pragma unroll
    for (int mt = 0; mt < 2; mt++) {
#pragma unroll
        for (int nt = 0; nt < 4; nt++) {
            size_t row = m0 + wm * 32 + mt * 16 + gid;
            size_t col = n0 + wn * 32 + nt * 8 + tig * 2;
#pragma unroll
            for (int e = 0; e < 4; e++) {
                size_t r = row + (size_t)(e >> 1) * 8;
                size_t c = col + (size_t)(e & 1);
                float v = acc[mt][nt][e] + bias[c];
                if (RELU) v = fmaxf(v, 0.f);
                C[r * N + c] = v;
                if (WT) T[c * (size_t)M + r] = v;
            }
        }
    }
}

// ============================================================================
// Split-K masked aggregation partial:
//   aggp[z][kc][i,c] = sum_{j in chunk} (adj==1 ? alpha : 0) * h[j,c]
//   degp[z][kc][i]   = count of adj==1 in chunk
// Double-buffered smem, grid (m-tiles, KC, 2), 128 threads.
// ============================================================================
template<int BM, int BN, int BK>
__global__ void __launch_bounds__(128)
agg_part(const int* __restrict__ adjA, const int* __restrict__ adjB,
         const float* __restrict__ alpha,
         const float* __restrict__ HtA, const float* __restrict__ HtB,
         float* __restrict__ aggp, int* __restrict__ degp, int K)
{
    constexpr int WM = BM / 32, WN = BN / 32, NT = WM * WN * 32;
    constexpr int LD = BK + 4;
    constexpr int F4 = BK / 4, RA = NT / F4, PA = BM / RA, PB = BN / RA;

    const int z = blockIdx.z;
    const int kc = blockIdx.y;
    const int* adj = z ? adjB : adjA;
    const float* Ht = z ? HtB : HtA;
    const int KCH = K / KC;
    const size_t kbase = (size_t)kc * KCH;

    __shared__ unsigned As[2][BM][LD];
    __shared__ unsigned Bs[2][BN][LD];
    __shared__ int sdeg[BM];

    const int tid = threadIdx.x, warp = tid >> 5, lane = tid & 31;
    const int wm = warp % WM, wn = warp / WM;
    const int gid = lane >> 2, tig = lane & 3;
    const size_t m0 = (size_t)blockIdx.x * BM;
    const int ax = tid % F4, ay = tid / F4;

    if (tid < BM) sdeg[tid] = 0;

    float acc[WM][WN * 2][4];
#pragma unroll
    for (int i = 0; i < WM; i++)
#pragma unroll
        for (int j = 0; j < WN * 2; j++)
#pragma unroll
            for (int e = 0; e < 4; e++) acc[i][j][e] = 0.f;

    int cnt[PA];
#pragma unroll
    for (int p = 0; p < PA; p++) cnt[p] = 0;

    int4 rma[PA]; float4 rva[PA]; float4 rb[PB];
    const int nIter = KCH / BK;

    auto ldA = [&](int it) {
#pragma unroll
        for (int p = 0; p < PA; p++) {
            size_t g = (m0 + p * RA + ay) * (size_t)K + kbase + (size_t)it * BK + ax * 4;
            rma[p] = *(const int4*)(adj + g);
            rva[p] = *(const float4*)(alpha + g);
        }
#pragma unroll
        for (int p = 0; p < PB; p++)
            rb[p] = *(const float4*)(Ht + (size_t)(p * RA + ay) * K + kbase + (size_t)it * BK + ax * 4);
    };
    auto stA = [&](int buf) {
#pragma unroll
        for (int p = 0; p < PA; p++) {
            int row = p * RA + ay;
            int mx = (rma[p].x == 1), my = (rma[p].y == 1);
            int mz = (rma[p].z == 1), mw = (rma[p].w == 1);
            cnt[p] += mx + my + mz + mw;
            As[buf][row][ax * 4 + 0] = f2t(mx ? rva[p].x : 0.f);
            As[buf][row][ax * 4 + 1] = f2t(my ? rva[p].y : 0.f);
            As[buf][row][ax * 4 + 2] = f2t(mz ? rva[p].z : 0.f);
            As[buf][row][ax * 4 + 3] = f2t(mw ? rva[p].w : 0.f);
        }
#pragma unroll
        for (int p = 0; p < PB; p++) {
            int row = p * RA + ay;
            Bs[buf][row][ax * 4 + 0] = f2t(rb[p].x);
            Bs[buf][row][ax * 4 + 1] = f2t(rb[p].y);
            Bs[buf][row][ax * 4 + 2] = f2t(rb[p].z);
            Bs[buf][row][ax * 4 + 3] = f2t(rb[p].w);
        }
    };

    ldA(0); stA(0);
    if (nIter > 1) ldA(1);
    __syncthreads();

    for (int it = 0; it < nIter; it++) {
        const int cur = it & 1;
        if (it + 1 < nIter) stA(cur ^ 1);
        if (it + 2 < nIter) ldA(it + 2);
#pragma unroll
        for (int ks = 0; ks < BK / 8; ks++) {
            unsigned af[WM][4], bf[WN * 2][2];
#pragma unroll
            for (int mt = 0; mt < WM; mt++) {
                int rr = wm * 32 + mt * 16 + gid;
                af[mt][0] = As[cur][rr    ][ks * 8 + tig];
                af[mt][1] = As[cur][rr + 8][ks * 8 + tig];
                af[mt][2] = As[cur][rr    ][ks * 8 + tig + 4];
                af[mt][3] = As[cur][rr + 8][ks * 8 + tig + 4];
            }
#pragma unroll
            for (int nt = 0; nt < WN * 2; nt++) {
                int cc = wn * 32 + nt * 8 + gid;
                bf[nt][0] = Bs[cur][cc][ks * 8 + tig];
                bf[nt][1] = Bs[cur][cc][ks * 8 + tig + 4];
            }
#pragma unroll
            for (int mt = 0; mt < WM; mt++)
#pragma unroll
                for (int nt = 0; nt < WN * 2; nt++)
                    mma8(acc[mt][nt], af[mt], bf[nt]);
        }
        __syncthreads();
    }

#pragma unroll
    for (int p = 0; p < PA; p++) atomicAdd(&sdeg[p * RA + ay], cnt[p]);
    __syncthreads();

    // write partials
    float* aout = aggp + ((size_t)z * KC + kc) * 4096 * 64;
    int*   dout = degp + ((size_t)z * KC + kc) * 4096;
    if (tid < BM) dout[m0 + tid] = sdeg[tid];
#pragma unroll
    for (int mt = 0; mt < WM; mt++)
#pragma unroll
        for (int nt = 0; nt < WN * 2; nt++) {
            size_t row = m0 + wm * 32 + mt * 16 + gid;
            size_t col = wn * 32 + nt * 8 + tig * 2;
#pragma unroll
            for (int e = 0; e < 4; e++) {
                size_t r = row + (size_t)(e >> 1) * 8;
                size_t c = col + (size_t)(e & 1);
                aout[r * 64 + c] = acc[mt][nt][e];
            }
        }
}

// reduce partials: out = deg ? sum(agg)*W00/deg + h : 0
__global__ void agg_finish(const float* __restrict__ aggp, const int* __restrict__ degp,
                           const float* __restrict__ HA, const float* __restrict__ HB,
                           const float* __restrict__ Wp,
                           float* __restrict__ OA, float* __restrict__ OB)
{
    const int L = 4096 * 64;
    int idx = blockIdx.x * blockDim.x + threadIdx.x;   // 0 .. 2L-1
    int z = idx >= L;
    int li = idx - z * L;
    int r = li >> 6;
    float s = 0.f; int d = 0;
    const float* ap = aggp + (size_t)z * KC * L;
    const int* dp = degp + (size_t)z * KC * 4096;
#pragma unroll
    for (int kc = 0; kc < KC; kc++) {
        s += ap[(size_t)kc * L + li];
        d += dp[kc * 4096 + r];
    }
    const float* H = z ? HB : HA;
    float* O = z ? OB : OA;
    float v = d ? s * Wp[0] / (float)d + H[li] : 0.f;
    O[li] = v;
}

// ============================================================================
// Classifier (deterministic two-stage reduction)
// ============================================================================
__global__ void clf_partial(const float* __restrict__ n0f, const float* __restrict__ n1f,
                            const float* __restrict__ w, float* __restrict__ part)
{
    const int L = 4096 * 64;
    const int TOT = 2 * L;
    const int chunk = 2048;
    int base = blockIdx.x * chunk;
    float s0 = 0.f, s1 = 0.f;
    for (int i = base + threadIdx.x; i < base + chunk; i += blockDim.x) {
        float f = (i < L) ? n0f[i] : n1f[i - L];
        s0 += f * w[i];
        s1 += f * w[TOT + i];
    }
    __shared__ float sm[8][2];
#pragma unroll
    for (int o = 16; o; o >>= 1) {
        s0 += __shfl_down_sync(0xffffffffu, s0, o);
        s1 += __shfl_down_sync(0xffffffffu, s1, o);
    }
    if ((threadIdx.x & 31) == 0) { sm[threadIdx.x >> 5][0] = s0; sm[threadIdx.x >> 5][1] = s1; }
    __syncthreads();
    if (threadIdx.x == 0) {
        float a = 0.f, b = 0.f;
        for (int i = 0; i < (int)(blockDim.x >> 5); i++) { a += sm[i][0]; b += sm[i][1]; }
        part[blockIdx.x * 2 + 0] = a;
        part[blockIdx.x * 2 + 1] = b;
    }
}

__global__ void clf_final(const float* __restrict__ part, const float* __restrict__ bias,
                          float* __restrict__ out, int nb)
{
    float s0 = 0.f, s1 = 0.f;
    for (int i = threadIdx.x; i < nb; i += blockDim.x) { s0 += part[i * 2]; s1 += part[i * 2 + 1]; }
    __shared__ float sm[8][2];
#pragma unroll
    for (int o = 16; o; o >>= 1) {
        s0 += __shfl_down_sync(0xffffffffu, s0, o);
        s1 += __shfl_down_sync(0xffffffffu, s1, o);
    }
    if ((threadIdx.x & 31) == 0) { sm[threadIdx.x >> 5][0] = s0; sm[threadIdx.x >> 5][1] = s1; }
    __syncthreads();
    if (threadIdx.x == 0) {
        float a = 0.f, b = 0.f;
        for (int i = 0; i < (int)(blockDim.x >> 5); i++) { a += sm[i][0]; b += sm[i][1]; }
        out[0] = a + bias[0];
        out[1] = b + bias[1];
    }
}

// ============================================================================
extern "C" void kernel_launch(void* const* d_in, const int* in_sizes, int n_in,
                              void* d_out, int out_size)
{
    const float* x1    = (const float*)d_in[0];
    const float* x2    = (const float*)d_in[1];
    const int*   adj1  = (const int*)d_in[2];
    const int*   adj2  = (const int*)d_in[3];
    const float* e1_w1 = (const float*)d_in[4];
    const float* e1_b1 = (const float*)d_in[5];
    const float* e1_w2 = (const float*)d_in[6];
    const float* e1_b2 = (const float*)d_in[7];
    const float* e1_w3 = (const float*)d_in[8];
    const float* e1_b3 = (const float*)d_in[9];
    const float* e2_w1 = (const float*)d_in[10];
    const float* e2_b1 = (const float*)d_in[11];
    const float* e2_w2 = (const float*)d_in[12];
    const float* e2_b2 = (const float*)d_in[13];
    const float* e2_w3 = (const float*)d_in[14];
    const float* e2_b3 = (const float*)d_in[15];
    const float* W     = (const float*)d_in[16];
    const float* alpha = (const float*)d_in[17];
    const float* clf_w = (const float*)d_in[18];
    const float* clf_b = (const float*)d_in[19];

    float *fc1p, *fc2p, *hp, *htp, *newp, *partp, *aggpp;
    int *degpp;
    cudaGetSymbolAddress((void**)&fc1p,  g_fc1);
    cudaGetSymbolAddress((void**)&fc2p,  g_fc2);
    cudaGetSymbolAddress((void**)&hp,    g_h);
    cudaGetSymbolAddress((void**)&htp,   g_ht);
    cudaGetSymbolAddress((void**)&newp,  g_new);
    cudaGetSymbolAddress((void**)&partp, g_part);
    cudaGetSymbolAddress((void**)&aggpp, g_aggp);
    cudaGetSymbolAddress((void**)&degpp, g_degp);

    // fc1: [4096,4096] x [256,4096]^T -> [4096,256]   (pipelined tf32)
    // grid: x = n-tile (fastest, shares A row-tile in L2), y = m-tile, z = graph
    gemm_pipe<64, 64, 32><<<dim3(4, 64, 2), 128>>>(
        x1, x2, e1_w1, e2_w1, e1_b1, e2_b1,
        fc1p, fc1p + 4096 * 256, 4096, 256, 4096);

    // fc2: [4096,256] x [128,256]^T -> [4096,128]     (split-tf32)
    gemm_tn<64, 64, 32, 2, false, false><<<dim3(64, 2, 2), 128>>>(
        fc1p, fc1p + 4096 * 256, e1_w2, e2_w2, e1_b2, e2_b2,
        fc2p, fc2p + 4096 * 128, nullptr, nullptr, 4096, 128, 256);

    // fc3+relu: [4096,128] x [64,128]^T -> [4096,64] (+ transposed copy)
    gemm_tn<64, 64, 32, 2, true, true><<<dim3(64, 1, 2), 128>>>(
        fc2p, fc2p + 4096 * 128, e1_w3, e2_w3, e1_b3, e2_b3,
        hp, hp + 4096 * 64, htp, htp + 64 * 4096, 4096, 64, 128);

    // split-K masked aggregation: 64 m-tiles x KC chunks x 2 graphs = 1024 CTAs
    agg_part<64, 64, 32><<<dim3(64, KC, 2), 128>>>(
        adj1, adj2, alpha, htp, htp + 64 * 4096, aggpp, degpp, 4096);

    agg_finish<<<2048, 256>>>(aggpp, degpp, hp, hp + 4096 * 64, W,
                              newp, newp + 4096 * 64);

    // classifier
    clf_partial<<<256, 256>>>(newp, newp + 4096 * 64, clf_w, partp);
    clf_final<<<1, 256>>>(partp, clf_b, (float*)d_out, 256);

    (void)in_sizes; (void)n_in; (void)out_size;
}

// round 5
// speedup vs baseline: 1.3138x; 1.0649x over previous
#include <cuda_runtime.h>
#include <cstdint>

#define DI __device__ __forceinline__

DI unsigned f2t(float x) { unsigned u; asm("cvt.rna.tf32.f32 %0, %1;" : "=r"(u) : "f"(x)); return u; }

DI void mma8(float c[4], const unsigned a[4], const unsigned b[2]) {
    asm("mma.sync.aligned.m16n8k8.row.col.f32.tf32.tf32.f32 "
        "{%0,%1,%2,%3}, {%4,%5,%6,%7}, {%8,%9}, {%0,%1,%2,%3};"
        : "+f"(c[0]), "+f"(c[1]), "+f"(c[2]), "+f"(c[3])
        : "r"(a[0]), "r"(a[1]), "r"(a[2]), "r"(a[3]), "r"(b[0]), "r"(b[1]));
}

// ---- scratch (device globals; no allocations allowed) ----
#define KC 8
__device__ float g_fc1[2][4096 * 256];
__device__ float g_fc2[2][4096 * 128];
__device__ float g_h  [2][4096 * 64];
__device__ float g_ht [2][64 * 4096];
__device__ float g_new[2][4096 * 64];
__device__ float g_aggp[2][KC][4096 * 64];
__device__ int   g_degp[2][KC][4096];
__device__ float g_part[512];
__device__ float g_w1cv[2][256 * 4096];

// ============================================================================
// Pre-pass: w1 -> RNA tf32 (stored as fp32 bits). fc1 then loads B raw,
// halving the in-loop cvt work while keeping R2-identical numerics.
// ============================================================================
__global__ void cvt_w1(const float* __restrict__ w0, const float* __restrict__ w1,
                       float* __restrict__ out)
{
    int idx = blockIdx.x * blockDim.x + threadIdx.x;      // float4 id, 2*262144 total
    int z = idx >= 262144;
    int li = idx - z * 262144;
    float4 v = ((const float4*)(z ? w1 : w0))[li];
    float4 o;
    o.x = __uint_as_float(f2t(v.x));
    o.y = __uint_as_float(f2t(v.y));
    o.z = __uint_as_float(f2t(v.z));
    o.w = __uint_as_float(f2t(v.w));
    ((float4*)out)[(size_t)z * 262144 + li] = o;
}

// ============================================================================
// fc1: C[4096,256] = X @ W1cv^T + b.  A: RNA cvt in STS path.  B: raw
// (pre-rounded w1cv).  BM=128, BN=64, BK=32, 256 thr (8 warps, 4m x 2n of
// 32x32 warp tiles).  Double-buffered smem + register prefetch.
// grid (nt=4, mt=32, z=2) = 256 CTAs.
// ============================================================================
#define LD1 36
#define AS1(s, r, c) dsm[(s) * (128 * LD1) + (r) * LD1 + (c)]
#define BS1(s, r, c) dsm[2 * 128 * LD1 + (s) * (64 * LD1) + (r) * LD1 + (c)]

__global__ void __launch_bounds__(256)
fc1_tf(const float* __restrict__ A0, const float* __restrict__ A1,
       const float* __restrict__ Bcv,
       const float* __restrict__ bias0, const float* __restrict__ bias1,
       float* __restrict__ C)
{
    extern __shared__ unsigned dsm[];
    constexpr int K = 4096, BK = 32;
    const int tid = threadIdx.x, warp = tid >> 5, lane = tid & 31;
    const int wm = warp & 3, wn = warp >> 2;          // 4 x 2 warps
    const int gid = lane >> 2, tig = lane & 3;
    const int z = blockIdx.z;
    const size_t m0 = (size_t)blockIdx.y * 128;
    const size_t n0 = (size_t)blockIdx.x * 64;
    const int ax = tid & 7, ay = tid >> 3;            // 8 float4 per 32-wide row

    const float* A = (z ? A1 : A0) + (m0 + ay) * (size_t)K + ax * 4;
    const float* B = Bcv + (size_t)z * 256 * 4096 + (n0 + ay) * (size_t)K + ax * 4;
    const float* bias = z ? bias1 : bias0;
    float* Cb = C + (size_t)z * 4096 * 256;

    float acc[2][4][4];
#pragma unroll
    for (int i = 0; i < 2; i++)
#pragma unroll
        for (int j = 0; j < 4; j++)
#pragma unroll
            for (int e = 0; e < 4; e++) acc[i][j][e] = 0.f;

    float4 ra[4]; uint4 rb[2];
    const int nIter = K / BK;                          // 128

    auto ldT = [&](int it) {
        const size_t ko = (size_t)it * BK;
#pragma unroll
        for (int p = 0; p < 4; p++)
            ra[p] = *(const float4*)(A + (size_t)p * 32 * K + ko);
#pragma unroll
        for (int p = 0; p < 2; p++)
            rb[p] = *(const uint4*)(B + (size_t)p * 32 * K + ko);
    };
    auto stT = [&](int s) {
#pragma unroll
        for (int p = 0; p < 4; p++) {
            uint4 t;
            t.x = f2t(ra[p].x); t.y = f2t(ra[p].y);
            t.z = f2t(ra[p].z); t.w = f2t(ra[p].w);
            *(uint4*)&AS1(s, p * 32 + ay, ax * 4) = t;
        }
#pragma unroll
        for (int p = 0; p < 2; p++)
            *(uint4*)&BS1(s, p * 32 + ay, ax * 4) = rb[p];
    };

    ldT(0); stT(0);
    ldT(1);
    __syncthreads();

    for (int it = 0; it < nIter; it++) {
        const int cur = it & 1;
        if (it + 1 < nIter) stT(cur ^ 1);
        if (it + 2 < nIter) ldT(it + 2);
#pragma unroll
        for (int ks = 0; ks < BK / 8; ks++) {
            unsigned af[2][4], bf[4][2];
#pragma unroll
            for (int mt = 0; mt < 2; mt++) {
                int rr = wm * 32 + mt * 16 + gid;
                af[mt][0] = AS1(cur, rr,     ks * 8 + tig);
                af[mt][1] = AS1(cur, rr + 8, ks * 8 + tig);
                af[mt][2] = AS1(cur, rr,     ks * 8 + tig + 4);
                af[mt][3] = AS1(cur, rr + 8, ks * 8 + tig + 4);
            }
#pragma unroll
            for (int nt = 0; nt < 4; nt++) {
                int cc = wn * 32 + nt * 8 + gid;
                bf[nt][0] = BS1(cur, cc, ks * 8 + tig);
                bf[nt][1] = BS1(cur, cc, ks * 8 + tig + 4);
            }
#pragma unroll
            for (int mt = 0; mt < 2; mt++)
#pragma unroll
                for (int nt = 0; nt < 4; nt++)
                    mma8(acc[mt][nt], af[mt], bf[nt]);
        }
        __syncthreads();
    }

#pragma unroll
    for (int mt = 0; mt < 2; mt++)
#pragma unroll
        for (int nt = 0; nt < 4; nt++) {
            size_t row = m0 + wm * 32 + mt * 16 + gid;
            size_t col = n0 + wn * 32 + nt * 8 + tig * 2;
#pragma unroll
            for (int e = 0; e < 4; e++) {
                size_t r = row + (size_t)(e >> 1) * 8;
                size_t c = col + (size_t)(e & 1);
                Cb[r * 256 + c] = acc[mt][nt][e] + bias[c];
            }
        }
}

// ============================================================================
// Single-buffered split-tf32 GEMM for fc2/fc3 (cheap layers, fp32-class acc).
// WT path stores the transposed copy pre-rounded to tf32 (feeds agg raw path).
// ============================================================================
template<int BM, int BN, int BK, int NS, bool RELU, bool WT>
__global__ void __launch_bounds__((BM / 32) * (BN / 32) * 32)
gemm_tn(const float* __restrict__ A0, const float* __restrict__ A1,
        const float* __restrict__ B0, const float* __restrict__ B1,
        const float* __restrict__ bias0, const float* __restrict__ bias1,
        float* __restrict__ C0, float* __restrict__ C1,
        float* __restrict__ T0, float* __restrict__ T1,
        int M, int N, int K)
{
    constexpr int WM = BM / 32, WN = BN / 32, NW = WM * WN, NT = NW * 32;
    constexpr int LD = BK + 4;
    constexpr int F4 = BK / 4, RA = NT / F4, PA = BM / RA, PB = BN / RA;

    const int z = blockIdx.z;
    const float* A = z ? A1 : A0;
    const float* B = z ? B1 : B0;
    const float* bias = z ? bias1 : bias0;
    float* C = z ? C1 : C0;
    float* T = z ? T1 : T0;

    __shared__ unsigned As[NS][BM][LD];
    __shared__ unsigned Bs[NS][BN][LD];

    const int tid = threadIdx.x, warp = tid >> 5, lane = tid & 31;
    const int wm = warp % WM, wn = warp / WM;
    const int gid = lane >> 2, tig = lane & 3;
    const size_t m0 = (size_t)blockIdx.x * BM;
    const size_t n0 = (size_t)blockIdx.y * BN;
    const int ax = tid % F4, ay = tid / F4;

    float acc[2][4][4];
#pragma unroll
    for (int i = 0; i < 2; i++)
#pragma unroll
        for (int j = 0; j < 4; j++)
#pragma unroll
            for (int e = 0; e < 4; e++) acc[i][j][e] = 0.f;

    float4 ra[PA], rb[PB];
#pragma unroll
    for (int p = 0; p < PA; p++)
        ra[p] = *(const float4*)(A + (m0 + p * RA + ay) * K + ax * 4);
#pragma unroll
    for (int p = 0; p < PB; p++)
        rb[p] = *(const float4*)(B + (n0 + p * RA + ay) * K + ax * 4);

    for (int k0 = 0; k0 < K; k0 += BK) {
#pragma unroll
        for (int p = 0; p < PA; p++) {
            int row = p * RA + ay;
            unsigned h0 = f2t(ra[p].x), h1 = f2t(ra[p].y), h2 = f2t(ra[p].z), h3 = f2t(ra[p].w);
            As[0][row][ax * 4 + 0] = h0; As[0][row][ax * 4 + 1] = h1;
            As[0][row][ax * 4 + 2] = h2; As[0][row][ax * 4 + 3] = h3;
            if (NS == 2) {
                As[NS - 1][row][ax * 4 + 0] = f2t(ra[p].x - __uint_as_float(h0));
                As[NS - 1][row][ax * 4 + 1] = f2t(ra[p].y - __uint_as_float(h1));
                As[NS - 1][row][ax * 4 + 2] = f2t(ra[p].z - __uint_as_float(h2));
                As[NS - 1][row][ax * 4 + 3] = f2t(ra[p].w - __uint_as_float(h3));
            }
        }
#pragma unroll
        for (int p = 0; p < PB; p++) {
            int row = p * RA + ay;
            unsigned h0 = f2t(rb[p].x), h1 = f2t(rb[p].y), h2 = f2t(rb[p].z), h3 = f2t(rb[p].w);
            Bs[0][row][ax * 4 + 0] = h0; Bs[0][row][ax * 4 + 1] = h1;
            Bs[0][row][ax * 4 + 2] = h2; Bs[0][row][ax * 4 + 3] = h3;
            if (NS == 2) {
                Bs[NS - 1][row][ax * 4 + 0] = f2t(rb[p].x - __uint_as_float(h0));
                Bs[NS - 1][row][ax * 4 + 1] = f2t(rb[p].y - __uint_as_float(h1));
                Bs[NS - 1][row][ax * 4 + 2] = f2t(rb[p].z - __uint_as_float(h2));
                Bs[NS - 1][row][ax * 4 + 3] = f2t(rb[p].w - __uint_as_float(h3));
            }
        }
        __syncthreads();

        if (k0 + BK < K) {
#pragma unroll
            for (int p = 0; p < PA; p++)
                ra[p] = *(const float4*)(A + (m0 + p * RA + ay) * K + (k0 + BK) + ax * 4);
#pragma unroll
            for (int p = 0; p < PB; p++)
                rb[p] = *(const float4*)(B + (n0 + p * RA + ay) * K + (k0 + BK) + ax * 4);
        }

#pragma unroll
        for (int ks = 0; ks < BK / 8; ks++) {
            unsigned af[NS][2][4], bf[NS][4][2];
#pragma unroll
            for (int s = 0; s < NS; s++) {
#pragma unroll
                for (int mt = 0; mt < 2; mt++) {
                    int rr = wm * 32 + mt * 16 + gid;
                    af[s][mt][0] = As[s][rr    ][ks * 8 + tig];
                    af[s][mt][1] = As[s][rr + 8][ks * 8 + tig];
                    af[s][mt][2] = As[s][rr    ][ks * 8 + tig + 4];
                    af[s][mt][3] = As[s][rr + 8][ks * 8 + tig + 4];
                }
#pragma unroll
                for (int nt = 0; nt < 4; nt++) {
                    int cc = wn * 32 + nt * 8 + gid;
                    bf[s][nt][0] = Bs[s][cc][ks * 8 + tig];
                    bf[s][nt][1] = Bs[s][cc][ks * 8 + tig + 4];
                }
            }
#pragma unroll
            for (int mt = 0; mt < 2; mt++)
#pragma unroll
                for (int nt = 0; nt < 4; nt++) {
                    mma8(acc[mt][nt], af[0][mt], bf[0][nt]);
                    if (NS == 2) {
                        mma8(acc[mt][nt], af[0][mt], bf[NS - 1][nt]);
                        mma8(acc[mt][nt], af[NS - 1][mt], bf[0][nt]);
                    }
                }
        }
        __syncthreads();
    }

#pragma unroll
    for (int mt = 0; mt < 2; mt++) {
#pragma unroll
        for (int nt = 0; nt < 4; nt++) {
            size_t row = m0 + wm * 32 + mt * 16 + gid;
            size_t col = n0 + wn * 32 + nt * 8 + tig * 2;
#pragma unroll
            for (int e = 0; e < 4; e++) {
                size_t r = row + (size_t)(e >> 1) * 8;
                size_t c = col + (size_t)(e & 1);
                float v = acc[mt][nt][e] + bias[c];
                if (RELU) v = fmaxf(v, 0.f);
                C[r * N + c] = v;
                if (WT) T[c * (size_t)M + r] = __uint_as_float(f2t(v));
            }
        }
    }
}

// ============================================================================
// Split-K masked aggregation partial — RNA cvt on masked alpha (R2 numerics),
// B raw (Ht pre-rounded by fc3 epilogue; f2t idempotent -> identical to R2).
// ============================================================================
template<int BM, int BN, int BK>
__global__ void __launch_bounds__(128)
agg_part(const int* __restrict__ adjA, const int* __restrict__ adjB,
         const float* __restrict__ alpha,
         const float* __restrict__ HtA, const float* __restrict__ HtB,
         float* __restrict__ aggp, int* __restrict__ degp, int K)
{
    constexpr int WM = BM / 32, WN = BN / 32, NT = WM * WN * 32;
    constexpr int LD = BK + 4;
    constexpr int F4 = BK / 4, RA = NT / F4, PA = BM / RA, PB = BN / RA;

    const int z = blockIdx.z;
    const int kc = blockIdx.y;
    const int* adj = z ? adjB : adjA;
    const float* Ht = z ? HtB : HtA;
    const int KCH = K / KC;
    const size_t kbase = (size_t)kc * KCH;

    __shared__ unsigned As[2][BM][LD];
    __shared__ unsigned Bs[2][BN][LD];
    __shared__ int sdeg[BM];

    const int tid = threadIdx.x, warp = tid >> 5, lane = tid & 31;
    const int wm = warp % WM, wn = warp / WM;
    const int gid = lane >> 2, tig = lane & 3;
    const size_t m0 = (size_t)blockIdx.x * BM;
    const int ax = tid % F4, ay = tid / F4;

    if (tid < BM) sdeg[tid] = 0;

    float acc[WM][WN * 2][4];
#pragma unroll
    for (int i = 0; i < WM; i++)
#pragma unroll
        for (int j = 0; j < WN * 2; j++)
#pragma unroll
            for (int e = 0; e < 4; e++) acc[i][j][e] = 0.f;

    int cnt[PA];
#pragma unroll
    for (int p = 0; p < PA; p++) cnt[p] = 0;

    int4 rma[PA]; float4 rva[PA]; uint4 rb[PB];
    const int nIter = KCH / BK;

    auto ldA = [&](int it) {
#pragma unroll
        for (int p = 0; p < PA; p++) {
            size_t g = (m0 + p * RA + ay) * (size_t)K + kbase + (size_t)it * BK + ax * 4;
            rma[p] = *(const int4*)(adj + g);
            rva[p] = *(const float4*)(alpha + g);
        }
#pragma unroll
        for (int p = 0; p < PB; p++)
            rb[p] = *(const uint4*)(Ht + (size_t)(p * RA + ay) * K + kbase + (size_t)it * BK + ax * 4);
    };
    auto stA = [&](int buf) {
#pragma unroll
        for (int p = 0; p < PA; p++) {
            int row = p * RA + ay;
            int mx = (rma[p].x == 1), my = (rma[p].y == 1);
            int mz = (rma[p].z == 1), mw = (rma[p].w == 1);
            cnt[p] += mx + my + mz + mw;
            As[buf][row][ax * 4 + 0] = f2t(mx ? rva[p].x : 0.f);
            As[buf][row][ax * 4 + 1] = f2t(my ? rva[p].y : 0.f);
            As[buf][row][ax * 4 + 2] = f2t(mz ? rva[p].z : 0.f);
            As[buf][row][ax * 4 + 3] = f2t(mw ? rva[p].w : 0.f);
        }
#pragma unroll
        for (int p = 0; p < PB; p++)
            *(uint4*)&Bs[buf][p * RA + ay][ax * 4] = rb[p];
    };

    ldA(0); stA(0);
    if (nIter > 1) ldA(1);
    __syncthreads();

    for (int it = 0; it < nIter; it++) {
        const int cur = it & 1;
        if (it + 1 < nIter) stA(cur ^ 1);
        if (it + 2 < nIter) ldA(it + 2);
#pragma unroll
        for (int ks = 0; ks < BK / 8; ks++) {
            unsigned af[WM][4], bf[WN * 2][2];
#pragma unroll
            for (int mt = 0; mt < WM; mt++) {
                int rr = wm * 32 + mt * 16 + gid;
                af[mt][0] = As[cur][rr    ][ks * 8 + tig];
                af[mt][1] = As[cur][rr + 8][ks * 8 + tig];
                af[mt][2] = As[cur][rr    ][ks * 8 + tig + 4];
                af[mt][3] = As[cur][rr + 8][ks * 8 + tig + 4];
            }
#pragma unroll
            for (int nt = 0; nt < WN * 2; nt++) {
                int cc = wn * 32 + nt * 8 + gid;
                bf[nt][0] = Bs[cur][cc][ks * 8 + tig];
                bf[nt][1] = Bs[cur][cc][ks * 8 + tig + 4];
            }
#pragma unroll
            for (int mt = 0; mt < WM; mt++)
#pragma unroll
                for (int nt = 0; nt < WN * 2; nt++)
                    mma8(acc[mt][nt], af[mt], bf[nt]);
        }
        __syncthreads();
    }

#pragma unroll
    for (int p = 0; p < PA; p++) atomicAdd(&sdeg[p * RA + ay], cnt[p]);
    __syncthreads();

    float* aout = aggp + ((size_t)z * KC + kc) * 4096 * 64;
    int*   dout = degp + ((size_t)z * KC + kc) * 4096;
    if (tid < BM) dout[m0 + tid] = sdeg[tid];
#pragma unroll
    for (int mt = 0; mt < WM; mt++)
#pragma unroll
        for (int nt = 0; nt < WN * 2; nt++) {
            size_t row = m0 + wm * 32 + mt * 16 + gid;
            size_t col = wn * 32 + nt * 8 + tig * 2;
#pragma unroll
            for (int e = 0; e < 4; e++) {
                size_t r = row + (size_t)(e >> 1) * 8;
                size_t c = col + (size_t)(e & 1);
                aout[r * 64 + c] = acc[mt][nt][e];
            }
        }
}

__global__ void agg_finish(const float* __restrict__ aggp, const int* __restrict__ degp,
                           const float* __restrict__ HA, const float* __restrict__ HB,
                           const float* __restrict__ Wp,
                           float* __restrict__ OA, float* __restrict__ OB)
{
    const int L = 4096 * 64;
    int idx = blockIdx.x * blockDim.x + threadIdx.x;
    int z = idx >= L;
    int li = idx - z * L;
    int r = li >> 6;
    float s = 0.f; int d = 0;
    const float* ap = aggp + (size_t)z * KC * L;
    const int* dp = degp + (size_t)z * KC * 4096;
#pragma unroll
    for (int kc = 0; kc < KC; kc++) {
        s += ap[(size_t)kc * L + li];
        d += dp[kc * 4096 + r];
    }
    const float* H = z ? HB : HA;
    float* O = z ? OB : OA;
    float v = d ? s * Wp[0] / (float)d + H[li] : 0.f;
    O[li] = v;
}

// ============================================================================
// Classifier (deterministic two-stage reduction)
// ============================================================================
__global__ void clf_partial(const float* __restrict__ n0f, const float* __restrict__ n1f,
                            const float* __restrict__ w, float* __restrict__ part)
{
    const int L = 4096 * 64;
    const int TOT = 2 * L;
    const int chunk = 2048;
    int base = blockIdx.x * chunk;
    float s0 = 0.f, s1 = 0.f;
    for (int i = base + threadIdx.x; i < base + chunk; i += blockDim.x) {
        float f = (i < L) ? n0f[i] : n1f[i - L];
        s0 += f * w[i];
        s1 += f * w[TOT + i];
    }
    __shared__ float sm[8][2];
#pragma unroll
    for (int o = 16; o; o >>= 1) {
        s0 += __shfl_down_sync(0xffffffffu, s0, o);
        s1 += __shfl_down_sync(0xffffffffu, s1, o);
    }
    if ((threadIdx.x & 31) == 0) { sm[threadIdx.x >> 5][0] = s0; sm[threadIdx.x >> 5][1] = s1; }
    __syncthreads();
    if (threadIdx.x == 0) {
        float a = 0.f, b = 0.f;
        for (int i = 0; i < (int)(blockDim.x >> 5); i++) { a += sm[i][0]; b += sm[i][1]; }
        part[blockIdx.x * 2 + 0] = a;
        part[blockIdx.x * 2 + 1] = b;
    }
}

__global__ void clf_final(const float* __restrict__ part, const float* __restrict__ bias,
                          float* __restrict__ out, int nb)
{
    float s0 = 0.f, s1 = 0.f;
    for (int i = threadIdx.x; i < nb; i += blockDim.x) { s0 += part[i * 2]; s1 += part[i * 2 + 1]; }
    __shared__ float sm[8][2];
#pragma unroll
    for (int o = 16; o; o >>= 1) {
        s0 += __shfl_down_sync(0xffffffffu, s0, o);
        s1 += __shfl_down_sync(0xffffffffu, s1, o);
    }
    if ((threadIdx.x & 31) == 0) { sm[threadIdx.x >> 5][0] = s0; sm[threadIdx.x >> 5][1] = s1; }
    __syncthreads();
    if (threadIdx.x == 0) {
        float a = 0.f, b = 0.f;
        for (int i = 0; i < (int)(blockDim.x >> 5); i++) { a += sm[i][0]; b += sm[i][1]; }
        out[0] = a + bias[0];
        out[1] = b + bias[1];
    }
}

// ============================================================================
extern "C" void kernel_launch(void* const* d_in, const int* in_sizes, int n_in,
                              void* d_out, int out_size)
{
    const float* x1    = (const float*)d_in[0];
    const float* x2    = (const float*)d_in[1];
    const int*   adj1  = (const int*)d_in[2];
    const int*   adj2  = (const int*)d_in[3];
    const float* e1_w1 = (const float*)d_in[4];
    const float* e1_b1 = (const float*)d_in[5];
    const float* e1_w2 = (const float*)d_in[6];
    const float* e1_b2 = (const float*)d_in[7];
    const float* e1_w3 = (const float*)d_in[8];
    const float* e1_b3 = (const float*)d_in[9];
    const float* e2_w1 = (const float*)d_in[10];
    const float* e2_b1 = (const float*)d_in[11];
    const float* e2_w2 = (const float*)d_in[12];
    const float* e2_b2 = (const float*)d_in[13];
    const float* e2_w3 = (const float*)d_in[14];
    const float* e2_b3 = (const float*)d_in[15];
    const float* W     = (const float*)d_in[16];
    const float* alpha = (const float*)d_in[17];
    const float* clf_w = (const float*)d_in[18];
    const float* clf_b = (const float*)d_in[19];

    float *fc1p, *fc2p, *hp, *htp, *newp, *partp, *aggpp, *w1cvp;
    int *degpp;
    cudaGetSymbolAddress((void**)&fc1p,  g_fc1);
    cudaGetSymbolAddress((void**)&fc2p,  g_fc2);
    cudaGetSymbolAddress((void**)&hp,    g_h);
    cudaGetSymbolAddress((void**)&htp,   g_ht);
    cudaGetSymbolAddress((void**)&newp,  g_new);
    cudaGetSymbolAddress((void**)&partp, g_part);
    cudaGetSymbolAddress((void**)&aggpp, g_aggp);
    cudaGetSymbolAddress((void**)&degpp, g_degp);
    cudaGetSymbolAddress((void**)&w1cvp, g_w1cv);

    const int FC1_SMEM = (2 * 128 * LD1 + 2 * 64 * LD1) * 4;   // 55296 B
    cudaFuncSetAttribute(fc1_tf, cudaFuncAttributeMaxDynamicSharedMemorySize, FC1_SMEM);

    // pre-pass: w1 -> RNA tf32
    cvt_w1<<<2048, 256>>>(e1_w1, e2_w1, w1cvp);

    // fc1: RNA-A / raw-B tf32 HMMA, grid (nt=4, mt=32, z=2) = 256 CTAs
    fc1_tf<<<dim3(4, 32, 2), 256, FC1_SMEM>>>(
        x1, x2, w1cvp, e1_b1, e2_b1, fc1p);

    // fc2: [4096,256] x [128,256]^T -> [4096,128]     (split-tf32)
    gemm_tn<64, 64, 32, 2, false, false><<<dim3(64, 2, 2), 128>>>(
        fc1p, fc1p + 4096 * 256, e1_w2, e2_w2, e1_b2, e2_b2,
        fc2p, fc2p + 4096 * 128, nullptr, nullptr, 4096, 128, 256);

    // fc3+relu: [4096,128] x [64,128]^T -> [4096,64] (+ tf32-rounded transpose)
    gemm_tn<64, 64, 32, 2, true, true><<<dim3(64, 1, 2), 128>>>(
        fc2p, fc2p + 4096 * 128, e1_w3, e2_w3, e1_b3, e2_b3,
        hp, hp + 4096 * 64, htp, htp + 64 * 4096, 4096, 64, 128);

    // split-K masked aggregation
    agg_part<64, 64, 32><<<dim3(64, KC, 2), 128>>>(
        adj1, adj2, alpha, htp, htp + 64 * 4096, aggpp, degpp, 4096);

    agg_finish<<<2048, 256>>>(aggpp, degpp, hp, hp + 4096 * 64, W,
                              newp, newp + 4096 * 64);

    // classifier
    clf_partial<<<256, 256>>>(newp, newp + 4096 * 64, clf_w, partp);
    clf_final<<<1, 256>>>(partp, clf_b, (float*)d_out, 256);

    (void)in_sizes; (void)n_in; (void)out_size;
}

// round 6
// speedup vs baseline: 1.4499x; 1.1035x over previous
#include <cuda_runtime.h>
#include <cstdint>

#define DI __device__ __forceinline__

DI unsigned f2t(float x) { unsigned u; asm("cvt.rna.tf32.f32 %0, %1;" : "=r"(u) : "f"(x)); return u; }

DI void mma8(float c[4], const unsigned a[4], const unsigned b[2]) {
    asm("mma.sync.aligned.m16n8k8.row.col.f32.tf32.tf32.f32 "
        "{%0,%1,%2,%3}, {%4,%5,%6,%7}, {%8,%9}, {%0,%1,%2,%3};"
        : "+f"(c[0]), "+f"(c[1]), "+f"(c[2]), "+f"(c[3])
        : "r"(a[0]), "r"(a[1]), "r"(a[2]), "r"(a[3]), "r"(b[0]), "r"(b[1]));
}

// ---- scratch (device globals; no allocations allowed) ----
#define KC 8
__device__ float g_fc1[2][4096 * 256];
__device__ float g_fc2[2][4096 * 128];
__device__ float g_h  [2][4096 * 64];
__device__ float g_ht [2][64 * 4096];
__device__ float g_new[2][4096 * 64];
__device__ float g_aggp[2][KC][4096 * 64];
__device__ int   g_degp[2][KC][4096];
__device__ float g_part[512];
__device__ float g_w1cv[2][256 * 4096];

// ============================================================================
// Pre-pass: w1 -> RNA tf32 (stored as fp32 bits). fc1 loads B raw.
// ============================================================================
__global__ void cvt_w1(const float* __restrict__ w0, const float* __restrict__ w1,
                       float* __restrict__ out)
{
    int idx = blockIdx.x * blockDim.x + threadIdx.x;      // float4 id, 2*262144 total
    int z = idx >= 262144;
    int li = idx - z * 262144;
    float4 v = ((const float4*)(z ? w1 : w0))[li];
    float4 o;
    o.x = __uint_as_float(f2t(v.x));
    o.y = __uint_as_float(f2t(v.y));
    o.z = __uint_as_float(f2t(v.z));
    o.w = __uint_as_float(f2t(v.w));
    ((float4*)out)[(size_t)z * 262144 + li] = o;
}

// ============================================================================
// fc1: C[4096,256] = X @ W1cv^T + b.
// BM=128, BN=128, BK=32, 256 thr; 8 warps as 4m x 2n, warp tile 32x64
// (mt=2, nt=8) -> 16 mmas per 24 LDS per ks (tensor-pipe-bound, not LDS).
// A: RNA cvt in STS path; B raw (pre-rounded w1cv).
// Double-buffered smem + register prefetch. grid (nt=2, mt=32, z=2) = 128 CTAs.
// ============================================================================
#define LD1 36
#define AS1(s, r, c) dsm[(s) * (128 * LD1) + (r) * LD1 + (c)]
#define BS1(s, r, c) dsm[2 * 128 * LD1 + (s) * (128 * LD1) + (r) * LD1 + (c)]

__global__ void __launch_bounds__(256)
fc1_tf(const float* __restrict__ A0, const float* __restrict__ A1,
       const float* __restrict__ Bcv,
       const float* __restrict__ bias0, const float* __restrict__ bias1,
       float* __restrict__ C)
{
    extern __shared__ unsigned dsm[];
    constexpr int K = 4096, BK = 32;
    const int tid = threadIdx.x, warp = tid >> 5, lane = tid & 31;
    const int wm = warp & 3, wn = warp >> 2;          // 4 m-warps x 2 n-warps
    const int gid = lane >> 2, tig = lane & 3;
    const int z = blockIdx.z;
    const size_t m0 = (size_t)blockIdx.y * 128;
    const size_t n0 = (size_t)blockIdx.x * 128;
    const int ax = tid & 7, ay = tid >> 3;            // 8 float4 per 32-wide row, 32 rows/pass

    const float* A = (z ? A1 : A0) + (m0 + ay) * (size_t)K + ax * 4;
    const float* B = Bcv + (size_t)z * 256 * 4096 + (n0 + ay) * (size_t)K + ax * 4;
    const float* bias = z ? bias1 : bias0;
    float* Cb = C + (size_t)z * 4096 * 256;

    float acc[2][8][4];
#pragma unroll
    for (int i = 0; i < 2; i++)
#pragma unroll
        for (int j = 0; j < 8; j++)
#pragma unroll
            for (int e = 0; e < 4; e++) acc[i][j][e] = 0.f;

    float4 ra[4]; uint4 rb[4];
    const int nIter = K / BK;                          // 128

    auto ldT = [&](int it) {
        const size_t ko = (size_t)it * BK;
#pragma unroll
        for (int p = 0; p < 4; p++)
            ra[p] = *(const float4*)(A + (size_t)p * 32 * K + ko);
#pragma unroll
        for (int p = 0; p < 4; p++)
            rb[p] = *(const uint4*)(B + (size_t)p * 32 * K + ko);
    };
    auto stT = [&](int s) {
#pragma unroll
        for (int p = 0; p < 4; p++) {
            uint4 t;
            t.x = f2t(ra[p].x); t.y = f2t(ra[p].y);
            t.z = f2t(ra[p].z); t.w = f2t(ra[p].w);
            *(uint4*)&AS1(s, p * 32 + ay, ax * 4) = t;
        }
#pragma unroll
        for (int p = 0; p < 4; p++)
            *(uint4*)&BS1(s, p * 32 + ay, ax * 4) = rb[p];
    };

    ldT(0); stT(0);
    ldT(1);
    __syncthreads();

    for (int it = 0; it < nIter; it++) {
        const int cur = it & 1;
        if (it + 1 < nIter) stT(cur ^ 1);
        if (it + 2 < nIter) ldT(it + 2);
#pragma unroll
        for (int ks = 0; ks < BK / 8; ks++) {
            unsigned af[2][4], bf[8][2];
#pragma unroll
            for (int mt = 0; mt < 2; mt++) {
                int rr = wm * 32 + mt * 16 + gid;
                af[mt][0] = AS1(cur, rr,     ks * 8 + tig);
                af[mt][1] = AS1(cur, rr + 8, ks * 8 + tig);
                af[mt][2] = AS1(cur, rr,     ks * 8 + tig + 4);
                af[mt][3] = AS1(cur, rr + 8, ks * 8 + tig + 4);
            }
#pragma unroll
            for (int nt = 0; nt < 8; nt++) {
                int cc = wn * 64 + nt * 8 + gid;
                bf[nt][0] = BS1(cur, cc, ks * 8 + tig);
                bf[nt][1] = BS1(cur, cc, ks * 8 + tig + 4);
            }
#pragma unroll
            for (int mt = 0; mt < 2; mt++)
#pragma unroll
                for (int nt = 0; nt < 8; nt++)
                    mma8(acc[mt][nt], af[mt], bf[nt]);
        }
        __syncthreads();
    }

#pragma unroll
    for (int mt = 0; mt < 2; mt++)
#pragma unroll
        for (int nt = 0; nt < 8; nt++) {
            size_t row = m0 + wm * 32 + mt * 16 + gid;
            size_t col = n0 + wn * 64 + nt * 8 + tig * 2;
#pragma unroll
            for (int e = 0; e < 4; e++) {
                size_t r = row + (size_t)(e >> 1) * 8;
                size_t c = col + (size_t)(e & 1);
                Cb[r * 256 + c] = acc[mt][nt][e] + bias[c];
            }
        }
}

// ============================================================================
// Single-buffered split-tf32 GEMM for fc2/fc3 (cheap layers, fp32-class acc).
// WT path stores the transposed copy pre-rounded to tf32 (feeds agg raw path).
// ============================================================================
template<int BM, int BN, int BK, int NS, bool RELU, bool WT>
__global__ void __launch_bounds__((BM / 32) * (BN / 32) * 32)
gemm_tn(const float* __restrict__ A0, const float* __restrict__ A1,
        const float* __restrict__ B0, const float* __restrict__ B1,
        const float* __restrict__ bias0, const float* __restrict__ bias1,
        float* __restrict__ C0, float* __restrict__ C1,
        float* __restrict__ T0, float* __restrict__ T1,
        int M, int N, int K)
{
    constexpr int WM = BM / 32, WN = BN / 32, NW = WM * WN, NT = NW * 32;
    constexpr int LD = BK + 4;
    constexpr int F4 = BK / 4, RA = NT / F4, PA = BM / RA, PB = BN / RA;

    const int z = blockIdx.z;
    const float* A = z ? A1 : A0;
    const float* B = z ? B1 : B0;
    const float* bias = z ? bias1 : bias0;
    float* C = z ? C1 : C0;
    float* T = z ? T1 : T0;

    __shared__ unsigned As[NS][BM][LD];
    __shared__ unsigned Bs[NS][BN][LD];

    const int tid = threadIdx.x, warp = tid >> 5, lane = tid & 31;
    const int wm = warp % WM, wn = warp / WM;
    const int gid = lane >> 2, tig = lane & 3;
    const size_t m0 = (size_t)blockIdx.x * BM;
    const size_t n0 = (size_t)blockIdx.y * BN;
    const int ax = tid % F4, ay = tid / F4;

    float acc[2][4][4];
#pragma unroll
    for (int i = 0; i < 2; i++)
#pragma unroll
        for (int j = 0; j < 4; j++)
#pragma unroll
            for (int e = 0; e < 4; e++) acc[i][j][e] = 0.f;

    float4 ra[PA], rb[PB];
#pragma unroll
    for (int p = 0; p < PA; p++)
        ra[p] = *(const float4*)(A + (m0 + p * RA + ay) * K + ax * 4);
#pragma unroll
    for (int p = 0; p < PB; p++)
        rb[p] = *(const float4*)(B + (n0 + p * RA + ay) * K + ax * 4);

    for (int k0 = 0; k0 < K; k0 += BK) {
#pragma unroll
        for (int p = 0; p < PA; p++) {
            int row = p * RA + ay;
            unsigned h0 = f2t(ra[p].x), h1 = f2t(ra[p].y), h2 = f2t(ra[p].z), h3 = f2t(ra[p].w);
            As[0][row][ax * 4 + 0] = h0; As[0][row][ax * 4 + 1] = h1;
            As[0][row][ax * 4 + 2] = h2; As[0][row][ax * 4 + 3] = h3;
            if (NS == 2) {
                As[NS - 1][row][ax * 4 + 0] = f2t(ra[p].x - __uint_as_float(h0));
                As[NS - 1][row][ax * 4 + 1] = f2t(ra[p].y - __uint_as_float(h1));
                As[NS - 1][row][ax * 4 + 2] = f2t(ra[p].z - __uint_as_float(h2));
                As[NS - 1][row][ax * 4 + 3] = f2t(ra[p].w - __uint_as_float(h3));
            }
        }
#pragma unroll
        for (int p = 0; p < PB; p++) {
            int row = p * RA + ay;
            unsigned h0 = f2t(rb[p].x), h1 = f2t(rb[p].y), h2 = f2t(rb[p].z), h3 = f2t(rb[p].w);
            Bs[0][row][ax * 4 + 0] = h0; Bs[0][row][ax * 4 + 1] = h1;
            Bs[0][row][ax * 4 + 2] = h2; Bs[0][row][ax * 4 + 3] = h3;
            if (NS == 2) {
                Bs[NS - 1][row][ax * 4 + 0] = f2t(rb[p].x - __uint_as_float(h0));
                Bs[NS - 1][row][ax * 4 + 1] = f2t(rb[p].y - __uint_as_float(h1));
                Bs[NS - 1][row][ax * 4 + 2] = f2t(rb[p].z - __uint_as_float(h2));
                Bs[NS - 1][row][ax * 4 + 3] = f2t(rb[p].w - __uint_as_float(h3));
            }
        }
        __syncthreads();

        if (k0 + BK < K) {
#pragma unroll
            for (int p = 0; p < PA; p++)
                ra[p] = *(const float4*)(A + (m0 + p * RA + ay) * K + (k0 + BK) + ax * 4);
#pragma unroll
            for (int p = 0; p < PB; p++)
                rb[p] = *(const float4*)(B + (n0 + p * RA + ay) * K + (k0 + BK) + ax * 4);
        }

#pragma unroll
        for (int ks = 0; ks < BK / 8; ks++) {
            unsigned af[NS][2][4], bf[NS][4][2];
#pragma unroll
            for (int s = 0; s < NS; s++) {
#pragma unroll
                for (int mt = 0; mt < 2; mt++) {
                    int rr = wm * 32 + mt * 16 + gid;
                    af[s][mt][0] = As[s][rr    ][ks * 8 + tig];
                    af[s][mt][1] = As[s][rr + 8][ks * 8 + tig];
                    af[s][mt][2] = As[s][rr    ][ks * 8 + tig + 4];
                    af[s][mt][3] = As[s][rr + 8][ks * 8 + tig + 4];
                }
#pragma unroll
                for (int nt = 0; nt < 4; nt++) {
                    int cc = wn * 32 + nt * 8 + gid;
                    bf[s][nt][0] = Bs[s][cc][ks * 8 + tig];
                    bf[s][nt][1] = Bs[s][cc][ks * 8 + tig + 4];
                }
            }
#pragma unroll
            for (int mt = 0; mt < 2; mt++)
#pragma unroll
                for (int nt = 0; nt < 4; nt++) {
                    mma8(acc[mt][nt], af[0][mt], bf[0][nt]);
                    if (NS == 2) {
                        mma8(acc[mt][nt], af[0][mt], bf[NS - 1][nt]);
                        mma8(acc[mt][nt], af[NS - 1][mt], bf[0][nt]);
                    }
                }
        }
        __syncthreads();
    }

#pragma unroll
    for (int mt = 0; mt < 2; mt++) {
#pragma unroll
        for (int nt = 0; nt < 4; nt++) {
            size_t row = m0 + wm * 32 + mt * 16 + gid;
            size_t col = n0 + wn * 32 + nt * 8 + tig * 2;
#pragma unroll
            for (int e = 0; e < 4; e++) {
                size_t r = row + (size_t)(e >> 1) * 8;
                size_t c = col + (size_t)(e & 1);
                float v = acc[mt][nt][e] + bias[c];
                if (RELU) v = fmaxf(v, 0.f);
                C[r * N + c] = v;
                if (WT) T[c * (size_t)M + r] = __uint_as_float(f2t(v));
            }
        }
    }
}

// ============================================================================
// Split-K masked aggregation partial — RNA cvt on masked alpha, B raw
// (Ht pre-rounded by fc3 epilogue).
// ============================================================================
template<int BM, int BN, int BK>
__global__ void __launch_bounds__(128)
agg_part(const int* __restrict__ adjA, const int* __restrict__ adjB,
         const float* __restrict__ alpha,
         const float* __restrict__ HtA, const float* __restrict__ HtB,
         float* __restrict__ aggp, int* __restrict__ degp, int K)
{
    constexpr int WM = BM / 32, WN = BN / 32, NT = WM * WN * 32;
    constexpr int LD = BK + 4;
    constexpr int F4 = BK / 4, RA = NT / F4, PA = BM / RA, PB = BN / RA;

    const int z = blockIdx.z;
    const int kc = blockIdx.y;
    const int* adj = z ? adjB : adjA;
    const float* Ht = z ? HtB : HtA;
    const int KCH = K / KC;
    const size_t kbase = (size_t)kc * KCH;

    __shared__ unsigned As[2][BM][LD];
    __shared__ unsigned Bs[2][BN][LD];
    __shared__ int sdeg[BM];

    const int tid = threadIdx.x, warp = tid >> 5, lane = tid & 31;
    const int wm = warp % WM, wn = warp / WM;
    const int gid = lane >> 2, tig = lane & 3;
    const size_t m0 = (size_t)blockIdx.x * BM;
    const int ax = tid % F4, ay = tid / F4;

    if (tid < BM) sdeg[tid] = 0;

    float acc[WM][WN * 2][4];
#pragma unroll
    for (int i = 0; i < WM; i++)
#pragma unroll
        for (int j = 0; j < WN * 2; j++)
#pragma unroll
            for (int e = 0; e < 4; e++) acc[i][j][e] = 0.f;

    int cnt[PA];
#pragma unroll
    for (int p = 0; p < PA; p++) cnt[p] = 0;

    int4 rma[PA]; float4 rva[PA]; uint4 rb[PB];
    const int nIter = KCH / BK;

    auto ldA = [&](int it) {
#pragma unroll
        for (int p = 0; p < PA; p++) {
            size_t g = (m0 + p * RA + ay) * (size_t)K + kbase + (size_t)it * BK + ax * 4;
            rma[p] = *(const int4*)(adj + g);
            rva[p] = *(const float4*)(alpha + g);
        }
#pragma unroll
        for (int p = 0; p < PB; p++)
            rb[p] = *(const uint4*)(Ht + (size_t)(p * RA + ay) * K + kbase + (size_t)it * BK + ax * 4);
    };
    auto stA = [&](int buf) {
#pragma unroll
        for (int p = 0; p < PA; p++) {
            int row = p * RA + ay;
            int mx = (rma[p].x == 1), my = (rma[p].y == 1);
            int mz = (rma[p].z == 1), mw = (rma[p].w == 1);
            cnt[p] += mx + my + mz + mw;
            As[buf][row][ax * 4 + 0] = f2t(mx ? rva[p].x : 0.f);
            As[buf][row][ax * 4 + 1] = f2t(my ? rva[p].y : 0.f);
            As[buf][row][ax * 4 + 2] = f2t(mz ? rva[p].z : 0.f);
            As[buf][row][ax * 4 + 3] = f2t(mw ? rva[p].w : 0.f);
        }
#pragma unroll
        for (int p = 0; p < PB; p++)
            *(uint4*)&Bs[buf][p * RA + ay][ax * 4] = rb[p];
    };

    ldA(0); stA(0);
    if (nIter > 1) ldA(1);
    __syncthreads();

    for (int it = 0; it < nIter; it++) {
        const int cur = it & 1;
        if (it + 1 < nIter) stA(cur ^ 1);
        if (it + 2 < nIter) ldA(it + 2);
#pragma unroll
        for (int ks = 0; ks < BK / 8; ks++) {
            unsigned af[WM][4], bf[WN * 2][2];
#pragma unroll
            for (int mt = 0; mt < WM; mt++) {
                int rr = wm * 32 + mt * 16 + gid;
                af[mt][0] = As[cur][rr    ][ks * 8 + tig];
                af[mt][1] = As[cur][rr + 8][ks * 8 + tig];
                af[mt][2] = As[cur][rr    ][ks * 8 + tig + 4];
                af[mt][3] = As[cur][rr + 8][ks * 8 + tig + 4];
            }
#pragma unroll
            for (int nt = 0; nt < WN * 2; nt++) {
                int cc = wn * 32 + nt * 8 + gid;
                bf[nt][0] = Bs[cur][cc][ks * 8 + tig];
                bf[nt][1] = Bs[cur][cc][ks * 8 + tig + 4];
            }
#pragma unroll
            for (int mt = 0; mt < WM; mt++)
#pragma unroll
                for (int nt = 0; nt < WN * 2; nt++)
                    mma8(acc[mt][nt], af[mt], bf[nt]);
        }
        __syncthreads();
    }

#pragma unroll
    for (int p = 0; p < PA; p++) atomicAdd(&sdeg[p * RA + ay], cnt[p]);
    __syncthreads();

    float* aout = aggp + ((size_t)z * KC + kc) * 4096 * 64;
    int*   dout = degp + ((size_t)z * KC + kc) * 4096;
    if (tid < BM) dout[m0 + tid] = sdeg[tid];
#pragma unroll
    for (int mt = 0; mt < WM; mt++)
#pragma unroll
        for (int nt = 0; nt < WN * 2; nt++) {
            size_t row = m0 + wm * 32 + mt * 16 + gid;
            size_t col = wn * 32 + nt * 8 + tig * 2;
#pragma unroll
            for (int e = 0; e < 4; e++) {
                size_t r = row + (size_t)(e >> 1) * 8;
                size_t c = col + (size_t)(e & 1);
                aout[r * 64 + c] = acc[mt][nt][e];
            }
        }
}

__global__ void agg_finish(const float* __restrict__ aggp, const int* __restrict__ degp,
                           const float* __restrict__ HA, const float* __restrict__ HB,
                           const float* __restrict__ Wp,
                           float* __restrict__ OA, float* __restrict__ OB)
{
    const int L = 4096 * 64;
    int idx = blockIdx.x * blockDim.x + threadIdx.x;
    int z = idx >= L;
    int li = idx - z * L;
    int r = li >> 6;
    float s = 0.f; int d = 0;
    const float* ap = aggp + (size_t)z * KC * L;
    const int* dp = degp + (size_t)z * KC * 4096;
#pragma unroll
    for (int kc = 0; kc < KC; kc++) {
        s += ap[(size_t)kc * L + li];
        d += dp[kc * 4096 + r];
    }
    const float* H = z ? HB : HA;
    float* O = z ? OB : OA;
    float v = d ? s * Wp[0] / (float)d + H[li] : 0.f;
    O[li] = v;
}

// ============================================================================
// Classifier (deterministic two-stage reduction)
// ============================================================================
__global__ void clf_partial(const float* __restrict__ n0f, const float* __restrict__ n1f,
                            const float* __restrict__ w, float* __restrict__ part)
{
    const int L = 4096 * 64;
    const int TOT = 2 * L;
    const int chunk = 2048;
    int base = blockIdx.x * chunk;
    float s0 = 0.f, s1 = 0.f;
    for (int i = base + threadIdx.x; i < base + chunk; i += blockDim.x) {
        float f = (i < L) ? n0f[i] : n1f[i - L];
        s0 += f * w[i];
        s1 += f * w[TOT + i];
    }
    __shared__ float sm[8][2];
#pragma unroll
    for (int o = 16; o; o >>= 1) {
        s0 += __shfl_down_sync(0xffffffffu, s0, o);
        s1 += __shfl_down_sync(0xffffffffu, s1, o);
    }
    if ((threadIdx.x & 31) == 0) { sm[threadIdx.x >> 5][0] = s0; sm[threadIdx.x >> 5][1] = s1; }
    __syncthreads();
    if (threadIdx.x == 0) {
        float a = 0.f, b = 0.f;
        for (int i = 0; i < (int)(blockDim.x >> 5); i++) { a += sm[i][0]; b += sm[i][1]; }
        part[blockIdx.x * 2 + 0] = a;
        part[blockIdx.x * 2 + 1] = b;
    }
}

__global__ void clf_final(const float* __restrict__ part, const float* __restrict__ bias,
                          float* __restrict__ out, int nb)
{
    float s0 = 0.f, s1 = 0.f;
    for (int i = threadIdx.x; i < nb; i += blockDim.x) { s0 += part[i * 2]; s1 += part[i * 2 + 1]; }
    __shared__ float sm[8][2];
#pragma unroll
    for (int o = 16; o; o >>= 1) {
        s0 += __shfl_down_sync(0xffffffffu, s0, o);
        s1 += __shfl_down_sync(0xffffffffu, s1, o);
    }
    if ((threadIdx.x & 31) == 0) { sm[threadIdx.x >> 5][0] = s0; sm[threadIdx.x >> 5][1] = s1; }
    __syncthreads();
    if (threadIdx.x == 0) {
        float a = 0.f, b = 0.f;
        for (int i = 0; i < (int)(blockDim.x >> 5); i++) { a += sm[i][0]; b += sm[i][1]; }
        out[0] = a + bias[0];
        out[1] = b + bias[1];
    }
}

// ============================================================================
extern "C" void kernel_launch(void* const* d_in, const int* in_sizes, int n_in,
                              void* d_out, int out_size)
{
    const float* x1    = (const float*)d_in[0];
    const float* x2    = (const float*)d_in[1];
    const int*   adj1  = (const int*)d_in[2];
    const int*   adj2  = (const int*)d_in[3];
    const float* e1_w1 = (const float*)d_in[4];
    const float* e1_b1 = (const float*)d_in[5];
    const float* e1_w2 = (const float*)d_in[6];
    const float* e1_b2 = (const float*)d_in[7];
    const float* e1_w3 = (const float*)d_in[8];
    const float* e1_b3 = (const float*)d_in[9];
    const float* e2_w1 = (const float*)d_in[10];
    const float* e2_b1 = (const float*)d_in[11];
    const float* e2_w2 = (const float*)d_in[12];
    const float* e2_b2 = (const float*)d_in[13];
    const float* e2_w3 = (const float*)d_in[14];
    const float* e2_b3 = (const float*)d_in[15];
    const float* W     = (const float*)d_in[16];
    const float* alpha = (const float*)d_in[17];
    const float* clf_w = (const float*)d_in[18];
    const float* clf_b = (const float*)d_in[19];

    float *fc1p, *fc2p, *hp, *htp, *newp, *partp, *aggpp, *w1cvp;
    int *degpp;
    cudaGetSymbolAddress((void**)&fc1p,  g_fc1);
    cudaGetSymbolAddress((void**)&fc2p,  g_fc2);
    cudaGetSymbolAddress((void**)&hp,    g_h);
    cudaGetSymbolAddress((void**)&htp,   g_ht);
    cudaGetSymbolAddress((void**)&newp,  g_new);
    cudaGetSymbolAddress((void**)&partp, g_part);
    cudaGetSymbolAddress((void**)&aggpp, g_aggp);
    cudaGetSymbolAddress((void**)&degpp, g_degp);
    cudaGetSymbolAddress((void**)&w1cvp, g_w1cv);

    const int FC1_SMEM = (2 * 128 * LD1 + 2 * 128 * LD1) * 4;   // 73728 B
    cudaFuncSetAttribute(fc1_tf, cudaFuncAttributeMaxDynamicSharedMemorySize, FC1_SMEM);

    // pre-pass: w1 -> RNA tf32
    cvt_w1<<<2048, 256>>>(e1_w1, e2_w1, w1cvp);

    // fc1: grid (nt=2, mt=32, z=2) = 128 CTAs, one wave
    fc1_tf<<<dim3(2, 32, 2), 256, FC1_SMEM>>>(
        x1, x2, w1cvp, e1_b1, e2_b1, fc1p);

    // fc2: [4096,256] x [128,256]^T -> [4096,128]     (split-tf32)
    gemm_tn<64, 64, 32, 2, false, false><<<dim3(64, 2, 2), 128>>>(
        fc1p, fc1p + 4096 * 256, e1_w2, e2_w2, e1_b2, e2_b2,
        fc2p, fc2p + 4096 * 128, nullptr, nullptr, 4096, 128, 256);

    // fc3+relu: [4096,128] x [64,128]^T -> [4096,64] (+ tf32-rounded transpose)
    gemm_tn<64, 64, 32, 2, true, true><<<dim3(64, 1, 2), 128>>>(
        fc2p, fc2p + 4096 * 128, e1_w3, e2_w3, e1_b3, e2_b3,
        hp, hp + 4096 * 64, htp, htp + 64 * 4096, 4096, 64, 128);

    // split-K masked aggregation
    agg_part<64, 64, 32><<<dim3(64, KC, 2), 128>>>(
        adj1, adj2, alpha, htp, htp + 64 * 4096, aggpp, degpp, 4096);

    agg_finish<<<2048, 256>>>(aggpp, degpp, hp, hp + 4096 * 64, W,
                              newp, newp + 4096 * 64);

    // classifier
    clf_partial<<<256, 256>>>(newp, newp + 4096 * 64, clf_w, partp);
    clf_final<<<1, 256>>>(partp, clf_b, (float*)d_out, 256);

    (void)in_sizes; (void)n_in; (void)out_size;
}